// round 7
// baseline (speedup 1.0000x reference)
#include <cuda_runtime.h>
#include <cuda_bf16.h>
#include <math.h>
#include <stdint.h>

#define NN   8192
#define DEG  8
#define NH   4
#define NF   768
#define NHD  3072
#define ND   768
#define NBG  8
#define NPG  1024
#define NQ   16
#define NROW 128   // NBG*NQ

// ---------------- scratch (static device memory; no allocation) ----------------
__device__ __nv_bfloat16 g_feat16[(size_t)NN * NHD]; // GEMM output (feat), bf16
__device__ __nv_bfloat16 g_h16[(size_t)NN * NHD];    // aggregate output (pre-LN), bf16
__device__ __nv_bfloat16 g_a16[(size_t)NN * NHD];    // bf16 GEMM A operand
__device__ __nv_bfloat16 g_bT[(size_t)NHD * NHD];    // bf16 transposed weights [M][K]
__device__ float g_el[NN * NH];
__device__ float g_er[NN * NH];
__device__ float g_m1[(size_t)NN * NF];
__device__ float g_rep[(size_t)NN * NF];
__device__ float g_S[(size_t)NROW * NN];
__device__ float g_colsum[NHD];
__device__ float g_colsq[NHD];
__device__ float g_colA[NHD];
__device__ float g_colB[NHD];

// ================= bf16 tensor-core GEMM (mma.sync m16n8k16) =================
// C[N x 3072] = A[N x K](bf16) @ Bt[3072 x K]^T(bf16), fp32 accum, bf16 out.
// 512 threads = 16 warps (4x4), block tile 256x256x32, warp tile 64x64.
// Fused epilogue: el/er partial dots (feat . attn_l/r) + atomicAdd.
// smem tiles [256 rows][32 bf16] padded to 20 words/row (conflict-free, 16B aligned).
#define BK2   32
#define ROWW  20                    // 32-bit words per smem row
#define TILE_W (256 * ROWW)         // words per tile buffer
#define GEMM_SMEM (4 * TILE_W * 4)  // 2 operands x 2 buffers = 80KB

__device__ __forceinline__ void cp_async16(void* dst, const void* src) {
    unsigned int s = (unsigned int)__cvta_generic_to_shared(dst);
    asm volatile("cp.async.cg.shared.global [%0], [%1], 16;" :: "r"(s), "l"(src));
}

__device__ __forceinline__ void bf16_load_tiles(
    uint32_t* As, uint32_t* Bs, const __nv_bfloat16* Ab, const __nv_bfloat16* Bb,
    int buf, int k0, int tid, int K)
{
#pragma unroll
    for (int i = 0; i < 2; i++) {
        int li = tid + i * 512;          // 0..1023
        int r = li >> 2, ch = li & 3;    // 256 rows x 4 16B-chunks
        cp_async16((char*)(As + buf * TILE_W) + r * 80 + ch * 16,
                   Ab + (size_t)r * K + k0 + ch * 8);
    }
#pragma unroll
    for (int i = 0; i < 2; i++) {
        int li = tid + i * 512;
        int r = li >> 2, ch = li & 3;
        cp_async16((char*)(Bs + buf * TILE_W) + r * 80 + ch * 16,
                   Bb + (size_t)r * K + k0 + ch * 8);
    }
    asm volatile("cp.async.commit_group;");
}

__global__ __launch_bounds__(512) void bf16_gemm_kernel(
    const __nv_bfloat16* __restrict__ A, const __nv_bfloat16* __restrict__ Bt,
    __nv_bfloat16* __restrict__ C, int K,
    const float* __restrict__ al, const float* __restrict__ ar,
    float* __restrict__ el, float* __restrict__ er)
{
    extern __shared__ uint32_t sm[];
    uint32_t* As = sm;                 // 2 x TILE_W
    uint32_t* Bs = sm + 2 * TILE_W;    // 2 x TILE_W
    int tid = threadIdx.x;
    int lane = tid & 31, wid = tid >> 5;
    int wm = (wid & 3) * 64, wn = (wid >> 2) * 64;
    int g = lane >> 2, tig = lane & 3;
    const __nv_bfloat16* Ab = A + (size_t)blockIdx.y * 256 * K;
    const __nv_bfloat16* Bb = Bt + (size_t)blockIdx.x * 256 * K;

    float c[4][8][4];
#pragma unroll
    for (int mt = 0; mt < 4; mt++)
#pragma unroll
        for (int nt = 0; nt < 8; nt++)
#pragma unroll
            for (int i = 0; i < 4; i++) c[mt][nt][i] = 0.f;

    bf16_load_tiles(As, Bs, Ab, Bb, 0, 0, tid, K);
    int nk = K / BK2;
    for (int t = 0; t < nk; t++) {
        int buf = t & 1;
        asm volatile("cp.async.wait_group 0;" ::: "memory");
        __syncthreads();
        if (t + 1 < nk)
            bf16_load_tiles(As, Bs, Ab, Bb, buf ^ 1, (t + 1) * BK2, tid, K);
        const uint32_t* A2 = As + buf * TILE_W;
        const uint32_t* B2 = Bs + buf * TILE_W;
#pragma unroll
        for (int kk2 = 0; kk2 < 2; kk2++) {
            int kw = kk2 * 8;
            unsigned a[4][4], b[8][2];
#pragma unroll
            for (int mt = 0; mt < 4; mt++) {
                int base = (wm + mt * 16 + g) * ROWW + kw + tig;
                a[mt][0] = A2[base];
                a[mt][1] = A2[base + 8 * ROWW];
                a[mt][2] = A2[base + 4];
                a[mt][3] = A2[base + 8 * ROWW + 4];
            }
#pragma unroll
            for (int nt = 0; nt < 8; nt++) {
                int base = (wn + nt * 8 + g) * ROWW + kw + tig;
                b[nt][0] = B2[base];
                b[nt][1] = B2[base + 4];
            }
#pragma unroll
            for (int mt = 0; mt < 4; mt++)
#pragma unroll
                for (int nt = 0; nt < 8; nt++)
                    asm volatile(
                        "mma.sync.aligned.m16n8k16.row.col.f32.bf16.bf16.f32 "
                        "{%0,%1,%2,%3}, {%4,%5,%6,%7}, {%8,%9}, {%0,%1,%2,%3};"
                        : "+f"(c[mt][nt][0]), "+f"(c[mt][nt][1]),
                          "+f"(c[mt][nt][2]), "+f"(c[mt][nt][3])
                        : "r"(a[mt][0]), "r"(a[mt][1]), "r"(a[mt][2]), "r"(a[mt][3]),
                          "r"(b[nt][0]), "r"(b[nt][1]));
        }
        __syncthreads();
    }

    // ---- epilogue: bf16 store + fused el/er partial dots ----
    __nv_bfloat16* Cb = C + (size_t)(blockIdx.y * 256) * NHD + blockIdx.x * 256;
    float pel[8], per[8];
#pragma unroll
    for (int i = 0; i < 8; i++) { pel[i] = 0.f; per[i] = 0.f; }
#pragma unroll
    for (int nt = 0; nt < 8; nt++) {
        int colg = blockIdx.x * 256 + wn + nt * 8 + 2 * tig;
        float a0 = al[colg], a1 = al[colg + 1];
        float r0 = ar[colg], r1 = ar[colg + 1];
#pragma unroll
        for (int mt = 0; mt < 4; mt++) {
            int row = wm + mt * 16 + g;
            int col = wn + nt * 8 + 2 * tig;
            *(__nv_bfloat162*)(Cb + (size_t)row * NHD + col) =
                __floats2bfloat162_rn(c[mt][nt][0], c[mt][nt][1]);
            *(__nv_bfloat162*)(Cb + (size_t)(row + 8) * NHD + col) =
                __floats2bfloat162_rn(c[mt][nt][2], c[mt][nt][3]);
            pel[mt * 2]     += c[mt][nt][0] * a0 + c[mt][nt][1] * a1;
            pel[mt * 2 + 1] += c[mt][nt][2] * a0 + c[mt][nt][3] * a1;
            per[mt * 2]     += c[mt][nt][0] * r0 + c[mt][nt][1] * r1;
            per[mt * 2 + 1] += c[mt][nt][2] * r0 + c[mt][nt][3] * r1;
        }
    }
    // reduce across the 4 tig lanes sharing each row
#pragma unroll
    for (int off = 1; off <= 2; off <<= 1)
#pragma unroll
        for (int i = 0; i < 8; i++) {
            pel[i] += __shfl_xor_sync(0xffffffffu, pel[i], off);
            per[i] += __shfl_xor_sync(0xffffffffu, per[i], off);
        }
    if (tig == 0) {
        int hd = (blockIdx.x * 256) / NF;   // head index (tile never crosses heads)
#pragma unroll
        for (int mt = 0; mt < 4; mt++)
#pragma unroll
            for (int hf = 0; hf < 2; hf++) {
                int n = blockIdx.y * 256 + wm + mt * 16 + hf * 8 + g;
                atomicAdd(&el[n * NH + hd], pel[mt * 2 + hf]);
                atomicAdd(&er[n * NH + hd], per[mt * 2 + hf]);
            }
    }
}

// ---------------- fp32 -> bf16 convert ----------------
__global__ void cvt16_kernel(const float* __restrict__ x, __nv_bfloat16* __restrict__ o, int n) {
    int i = blockIdx.x * 256 + threadIdx.x;
    if (i < n) o[i] = __float2bfloat16(x[i]);
}

// ---------------- W[K][M] -> Bt[M][K] bf16 transpose ----------------
__global__ __launch_bounds__(256) void wtrans_kernel(
    const float* __restrict__ W, __nv_bfloat16* __restrict__ Bt, int K, int M)
{
    __shared__ float t[32][33];
    int m0 = blockIdx.x * 32, k0 = blockIdx.y * 32;
    int tx = threadIdx.x & 31, ty = threadIdx.x >> 5;  // 32 x 8
#pragma unroll
    for (int i = 0; i < 32; i += 8)
        t[ty + i][tx] = W[(size_t)(k0 + ty + i) * M + m0 + tx];
    __syncthreads();
#pragma unroll
    for (int i = 0; i < 32; i += 8)
        Bt[(size_t)(m0 + ty + i) * K + k0 + tx] = __float2bfloat16(t[tx][ty + i]);
}

// ---------------- per-layer zeroing (colsums + el/er) ----------------
__global__ void prep_kernel() {
    int i = blockIdx.x * 256 + threadIdx.x;
    if (i < NHD) { g_colsum[i] = 0.f; g_colsq[i] = 0.f; }
    if (i < NN * NH) { g_el[i] = 0.f; g_er[i] = 0.f; }
}

// ---------------- edge softmax + aggregation (+bias), bf16 feat/h ----------------
__global__ __launch_bounds__(256) void aggregate_kernel(
    const __nv_bfloat16* __restrict__ feat, const float* __restrict__ el,
    const float* __restrict__ er, const int* __restrict__ esrc,
    const float* __restrict__ bias, __nv_bfloat16* __restrict__ outh)
{
    int n = blockIdx.x;
    __shared__ int   ssrc[DEG];
    __shared__ float salpha[NH * DEG];
    int tid = threadIdx.x;
    if (tid < DEG) ssrc[tid] = esrc[n * DEG + tid];
    __syncthreads();
    if (tid < 32) {
        int h = tid >> 3, k = tid & 7;
        float e = el[ssrc[k] * NH + h] + er[n * NH + h];
        e = e > 0.f ? e : 0.2f * e;
        float m = e;
#pragma unroll
        for (int o = 4; o; o >>= 1) m = fmaxf(m, __shfl_xor_sync(0xffffffffu, m, o));
        float a = __expf(e - m);
        float s = a;
#pragma unroll
        for (int o = 4; o; o >>= 1) s += __shfl_xor_sync(0xffffffffu, s, o);
        salpha[tid] = a / s;
    }
    __syncthreads();
    const __nv_bfloat162* f2 = (const __nv_bfloat162*)feat;
    __nv_bfloat162* o2 = (__nv_bfloat162*)outh;
    for (int c2 = tid; c2 < NHD / 2; c2 += 256) {
        int h = c2 / (NF / 2);
        float accx = bias[2 * c2], accy = bias[2 * c2 + 1];
#pragma unroll
        for (int k = 0; k < DEG; k++) {
            float w = salpha[h * DEG + k];
            float2 v = __bfloat1622float2(f2[(size_t)ssrc[k] * (NHD / 2) + c2]);
            accx += w * v.x; accy += w * v.y;
        }
        o2[(size_t)n * (NHD / 2) + c2] = __floats2bfloat162_rn(accx, accy);
    }
}

// ---------------- column stats (LayerNorm over axis 0), bf16 input ----------------
__global__ __launch_bounds__(256) void colstats_kernel(const __nv_bfloat16* __restrict__ x) {
    int c2 = blockIdx.x * 256 + threadIdx.x;   // 0..1535 (pair index)
    int r0 = blockIdx.y * 256;
    const __nv_bfloat162* x2 = (const __nv_bfloat162*)x;
    float s0 = 0.f, s1 = 0.f, q0 = 0.f, q1 = 0.f;
    for (int r = r0; r < r0 + 256; r++) {
        float2 v = __bfloat1622float2(x2[(size_t)r * (NHD / 2) + c2]);
        s0 += v.x; q0 += v.x * v.x;
        s1 += v.y; q1 += v.y * v.y;
    }
    atomicAdd(&g_colsum[2 * c2], s0);
    atomicAdd(&g_colsum[2 * c2 + 1], s1);
    atomicAdd(&g_colsq[2 * c2], q0);
    atomicAdd(&g_colsq[2 * c2 + 1], q1);
}

__global__ void colfin_kernel(const float* __restrict__ gamma, const float* __restrict__ beta) {
    int c = blockIdx.x * 256 + threadIdx.x;
    if (c >= NHD) return;
    float mu  = g_colsum[c] * (1.f / NN);
    float var = g_colsq[c] * (1.f / NN) - mu * mu;
    float rs  = rsqrtf(var + 1e-5f);
    float a   = rs * gamma[c];
    g_colA[c] = a;
    g_colB[c] = beta[c] - mu * a;
}

// ---------------- LN + PReLU epilogues (fused bf16 convert / head-mean) ----------------
__global__ __launch_bounds__(256) void lnfuse1_kernel(
    const __nv_bfloat16* __restrict__ h, const float* __restrict__ pa,
    __nv_bfloat16* __restrict__ a16, float* __restrict__ m1)
{
    int n = blockIdx.x;
    for (int f = threadIdx.x; f < NF; f += 256) {
        float s = 0.f;
#pragma unroll
        for (int hh = 0; hh < 4; hh++) {
            int c = hh * NF + f;
            float y = g_colA[c] * __bfloat162float(h[(size_t)n * NHD + c]) + g_colB[c];
            y = y > 0.f ? y : pa[c] * y;
            a16[(size_t)n * NHD + c] = __float2bfloat16(y);
            s += y;
        }
        m1[(size_t)n * NF + f] = 0.25f * s;
    }
}

__global__ __launch_bounds__(256) void lnfuse2_kernel(
    const __nv_bfloat16* __restrict__ h, const float* __restrict__ pa)
{
    int n = blockIdx.x;
    for (int f = threadIdx.x; f < NF; f += 256) {
        float s = 0.f;
#pragma unroll
        for (int hh = 0; hh < 4; hh++) {
            int c = hh * NF + f;
            float y = g_colA[c] * __bfloat162float(h[(size_t)n * NHD + c]) + g_colB[c];
            y = y > 0.f ? y : pa[c] * y;
            s += y;
        }
        g_rep[(size_t)n * NF + f] = fmaxf(g_m1[(size_t)n * NF + f], 0.25f * s);
    }
}

// ---------------- sims: S[128 x 8192] = Qe @ rep^T ----------------
__global__ __launch_bounds__(256) void simgemm_kernel(
    const float* __restrict__ Qe, const float* __restrict__ R)
{
    __shared__ float Qs[128][33];
    __shared__ float Rs[32][33];
    int tid = threadIdx.x;
    int n0 = blockIdx.x * 32;
    float acc[16];
#pragma unroll
    for (int i = 0; i < 16; i++) acc[i] = 0.f;
    int n = tid & 31, rb = tid >> 5;

    for (int k0 = 0; k0 < ND; k0 += 32) {
#pragma unroll
        for (int t = 0; t < 16; t++) {
            int li = tid + t * 256;
            Qs[li >> 5][li & 31] = Qe[(size_t)(li >> 5) * ND + k0 + (li & 31)];
        }
#pragma unroll
        for (int t = 0; t < 4; t++) {
            int li = tid + t * 256;
            Rs[li >> 5][li & 31] = R[(size_t)(n0 + (li >> 5)) * ND + k0 + (li & 31)];
        }
        __syncthreads();
#pragma unroll
        for (int kk = 0; kk < 32; kk++) {
            float b = Rs[n][kk];
#pragma unroll
            for (int i = 0; i < 16; i++)
                acc[i] += Qs[rb + 8 * i][kk] * b;
        }
        __syncthreads();
    }
#pragma unroll
    for (int i = 0; i < 16; i++)
        g_S[(size_t)(rb + 8 * i) * NN + n0 + n] = acc[i];
}

// ---------------- output zero ----------------
__global__ void zeroout_kernel(float* out) {
    if (threadIdx.x < 3) out[threadIdx.x] = 0.f;
}

// ---------------- losses ----------------
__device__ __forceinline__ float warpSumF(float v) {
#pragma unroll
    for (int o = 16; o; o >>= 1) v += __shfl_xor_sync(0xffffffffu, v, o);
    return v;
}

__device__ __forceinline__ float blockSumF(float v, float* sred, int tid) {
    v = warpSumF(v);
    if ((tid & 31) == 0) sred[tid >> 5] = v;
    __syncthreads();
    if (tid < 32) {
        float x = (tid < 16) ? sred[tid] : 0.f;
        x = warpSumF(x);
        if (tid == 0) sred[0] = x;
    }
    __syncthreads();
    float r = sred[0];
    __syncthreads();
    return r;
}

__device__ __forceinline__ float blockMaxF(float v, float* sred, int tid) {
#pragma unroll
    for (int o = 16; o; o >>= 1) v = fmaxf(v, __shfl_xor_sync(0xffffffffu, v, o));
    if ((tid & 31) == 0) sred[tid >> 5] = v;
    __syncthreads();
    if (tid < 32) {
        float x = (tid < 16) ? sred[tid] : -INFINITY;
#pragma unroll
        for (int o = 16; o; o >>= 1) x = fmaxf(x, __shfl_xor_sync(0xffffffffu, x, o));
        if (tid == 0) sred[0] = x;
    }
    __syncthreads();
    float r = sred[0];
    __syncthreads();
    return r;
}

__device__ void bitonic1024_desc(float* key, int* idx, int tid) {
    for (int k = 2; k <= 1024; k <<= 1) {
        for (int j = k >> 1; j > 0; j >>= 1) {
#pragma unroll 1
            for (int t = tid; t < 1024; t += 512) {
                int x = t ^ j;
                if (x > t) {
                    bool descSeg = ((t & k) == 0);
                    float ka = key[t], kb = key[x];
                    int   ia = idx[t], ib = idx[x];
                    bool aFirst = (ka > kb) || (ka == kb && ia < ib);
                    bool doSwap = descSeg ? (!aFirst) : aFirst;
                    if (doSwap) { key[t] = kb; key[x] = ka; idx[t] = ib; idx[x] = ia; }
                }
            }
            __syncthreads();
        }
    }
}

__global__ __launch_bounds__(512) void loss_kernel(const float* __restrict__ bert, float* __restrict__ out) {
    __shared__ float skey[1024];
    __shared__ int   sidx[1024];
    __shared__ float sred[16];
    __shared__ float sh_psim;
    int r = blockIdx.x;
    int g = r >> 4;
    int base = g * NPG;
    int tid = threadIdx.x;
    const float* Srow = g_S + (size_t)r * NN;

    skey[tid]       = bert[(size_t)r * NPG + tid];       sidx[tid]       = tid;
    skey[tid + 512] = bert[(size_t)r * NPG + tid + 512]; sidx[tid + 512] = tid + 512;
    __syncthreads();
    bitonic1024_desc(skey, sidx, tid);

    int i0 = sidx[tid], i1 = sidx[tid + 512];
    float v0 = Srow[base + i0], v1 = Srow[base + i1];
    __syncthreads();
    skey[tid] = v0;       sidx[tid] = tid;
    skey[tid + 512] = v1; sidx[tid + 512] = tid + 512;
    if (tid == 0) sh_psim = v0;
    __syncthreads();

    bitonic1024_desc(skey, sidx, tid);

    float L = 0.f;
    for (int i = 0; i < 1023; i++) {
        float yi = skey[i];
        int   pi = sidx[i];
        for (int j = i + 1 + tid; j < 1024; j += 512) {
            float s = yi - skey[j];
            float t = fminf(s, 50.f);
            float u = __logf(1.f + __expf(-t));
            L += u + ((pi > sidx[j]) ? t : 0.f);
        }
    }
    float Ltot = blockSumF(L, sred, tid);

    float mx = -INFINITY;
    for (int c = tid; c < NN; c += 512) mx = fmaxf(mx, Srow[c]);
    float m = blockMaxF(mx, sred, tid);

    float se = 0.f, s1 = 0.f, s2 = 0.f;
    for (int c = tid; c < NN; c += 512) {
        float x = Srow[c] - m;
        float e = __expf(x);
        se += e;
        if (c >= base && c < base + NPG) { s1 += e; s2 += x * e; }
    }
    se = blockSumF(se, sred, tid);
    s1 = blockSumF(s1, sred, tid);
    s2 = blockSumF(s2, sred, tid);

    if (tid == 0) {
        float lse = m + __logf(se);
        float cl  = lse - sh_psim;
        float ent = __logf(s1) - s2 / s1;
        atomicAdd(out + 0, cl  * (1.f / 128.f));
        atomicAdd(out + 2, ent * (1.f / 128.f));
        atomicAdd(out + 1, Ltot * (1.f / 67043328.f));
    }
}

// ---------------- launch ----------------
extern "C" void kernel_launch(void* const* d_in, const int* in_sizes, int n_in,
                              void* d_out, int out_size) {
    const float* x      = (const float*)d_in[0];
    const int*   esrc   = (const int*)d_in[1];
    const float* qe     = (const float*)d_in[3];
    const float* bert   = (const float*)d_in[4];
    const float* W1     = (const float*)d_in[5];
    const float* al1    = (const float*)d_in[6];
    const float* ar1    = (const float*)d_in[7];
    const float* b1     = (const float*)d_in[8];
    const float* gamma1 = (const float*)d_in[9];
    const float* beta1  = (const float*)d_in[10];
    const float* pa1    = (const float*)d_in[11];
    const float* W2     = (const float*)d_in[12];
    const float* al2    = (const float*)d_in[13];
    const float* ar2    = (const float*)d_in[14];
    const float* b2     = (const float*)d_in[15];
    const float* gamma2 = (const float*)d_in[16];
    const float* beta2  = (const float*)d_in[17];
    const float* pa2    = (const float*)d_in[18];
    float* out = (float*)d_out;

    float *el, *er, *m1, *rep;
    __nv_bfloat16 *feat16, *h16, *a16, *bT;
    cudaGetSymbolAddress((void**)&feat16, g_feat16);
    cudaGetSymbolAddress((void**)&h16,    g_h16);
    cudaGetSymbolAddress((void**)&el,     g_el);
    cudaGetSymbolAddress((void**)&er,     g_er);
    cudaGetSymbolAddress((void**)&m1,     g_m1);
    cudaGetSymbolAddress((void**)&rep,    g_rep);
    cudaGetSymbolAddress((void**)&a16,    g_a16);
    cudaGetSymbolAddress((void**)&bT,     g_bT);

    cudaFuncSetAttribute(bf16_gemm_kernel,
                         cudaFuncAttributeMaxDynamicSharedMemorySize, GEMM_SMEM);

    dim3 gGemm(NHD / 256, NN / 256);       // (12, 32)
    dim3 gStats(NHD / 512, NN / 256);      // (6, 32)

    zeroout_kernel<<<1, 32>>>(out);

    // ---- layer 1 ----
    cvt16_kernel<<<(NN * ND + 255) / 256, 256>>>(x, a16, NN * ND);
    wtrans_kernel<<<dim3(NHD / 32, ND / 32), 256>>>(W1, bT, ND, NHD);
    prep_kernel<<<(NN * NH + 255) / 256, 256>>>();
    bf16_gemm_kernel<<<gGemm, 512, GEMM_SMEM>>>(a16, bT, feat16, ND, al1, ar1, el, er);
    aggregate_kernel<<<NN, 256>>>(feat16, el, er, esrc, b1, h16);
    colstats_kernel<<<gStats, 256>>>(h16);
    colfin_kernel<<<NHD / 256, 256>>>(gamma1, beta1);
    lnfuse1_kernel<<<NN, 256>>>(h16, pa1, a16, m1);

    // ---- layer 2 ----
    wtrans_kernel<<<dim3(NHD / 32, NHD / 32), 256>>>(W2, bT, NHD, NHD);
    prep_kernel<<<(NN * NH + 255) / 256, 256>>>();
    bf16_gemm_kernel<<<gGemm, 512, GEMM_SMEM>>>(a16, bT, feat16, NHD, al2, ar2, el, er);
    aggregate_kernel<<<NN, 256>>>(feat16, el, er, esrc, b2, h16);
    colstats_kernel<<<gStats, 256>>>(h16);
    colfin_kernel<<<NHD / 256, 256>>>(gamma2, beta2);
    lnfuse2_kernel<<<NN, 256>>>(h16, pa2);

    // ---- similarities + losses ----
    simgemm_kernel<<<NN / 32, 256>>>(qe, rep);
    loss_kernel<<<NROW, 512>>>(bert, out);
}

// round 8
// speedup vs baseline: 1.3980x; 1.3980x over previous
#include <cuda_runtime.h>
#include <cuda_bf16.h>
#include <math.h>
#include <stdint.h>

#define NN   8192
#define DEG  8
#define NH   4
#define NF   768
#define NHD  3072
#define ND   768
#define NBG  8
#define NPG  1024
#define NQ   16
#define NROW 128   // NBG*NQ

// ---------------- scratch (static device memory; no allocation) ----------------
__device__ __nv_bfloat16 g_feat16[(size_t)NN * NHD]; // GEMM output (feat), bf16
__device__ __nv_bfloat16 g_h16[(size_t)NN * NHD];    // aggregate output (pre-LN), bf16
__device__ __nv_bfloat16 g_a16[(size_t)NN * NHD];    // bf16 GEMM A operand
__device__ __nv_bfloat16 g_bT[(size_t)NHD * NHD];    // bf16 transposed weights [M][K]
__device__ float g_el[NN * NH];
__device__ float g_er[NN * NH];
__device__ float g_m1[(size_t)NN * NF];
__device__ float g_rep[(size_t)NN * NF];
__device__ float g_S[(size_t)NROW * NN];
__device__ float g_colsum[NHD];
__device__ float g_colsq[NHD];
__device__ float g_colA[NHD];
__device__ float g_colB[NHD];

// ================= bf16 tensor-core GEMM (mma.sync m16n8k16) =================
// C[N x 3072] = A[N x K](bf16) @ Bt[3072 x K]^T(bf16), fp32 accum, bf16 out.
// 256 threads = 8 warps (2x4), block tile 128x256x32, warp tile 64x64.
// (52.7K regs/CTA < 64K -> no spill; R7's 512-thread 256x256 config spilled.)
// Fused epilogue: el/er partial dots (feat . attn_l/r) + atomicAdd.
#define BK2   32
#define ROWW  20                     // 32-bit words per smem row
#define TILE_AW (128 * ROWW)         // A tile words per buffer
#define TILE_BW (256 * ROWW)         // B tile words per buffer
#define GEMM_SMEM ((2 * TILE_AW + 2 * TILE_BW) * 4)   // 60KB

__device__ __forceinline__ void cp_async16(void* dst, const void* src) {
    unsigned int s = (unsigned int)__cvta_generic_to_shared(dst);
    asm volatile("cp.async.cg.shared.global [%0], [%1], 16;" :: "r"(s), "l"(src));
}

__device__ __forceinline__ void bf16_load_tiles(
    uint32_t* As, uint32_t* Bs, const __nv_bfloat16* Ab, const __nv_bfloat16* Bb,
    int buf, int k0, int tid, int K)
{
#pragma unroll
    for (int i = 0; i < 2; i++) {
        int li = tid + i * 256;          // 0..511
        int r = li >> 2, ch = li & 3;    // 128 rows x 4 16B-chunks
        cp_async16((char*)(As + buf * TILE_AW) + r * 80 + ch * 16,
                   Ab + (size_t)r * K + k0 + ch * 8);
    }
#pragma unroll
    for (int i = 0; i < 4; i++) {
        int li = tid + i * 256;          // 0..1023
        int r = li >> 2, ch = li & 3;    // 256 rows x 4 16B-chunks
        cp_async16((char*)(Bs + buf * TILE_BW) + r * 80 + ch * 16,
                   Bb + (size_t)r * K + k0 + ch * 8);
    }
    asm volatile("cp.async.commit_group;");
}

__global__ __launch_bounds__(256) void bf16_gemm_kernel(
    const __nv_bfloat16* __restrict__ A, const __nv_bfloat16* __restrict__ Bt,
    __nv_bfloat16* __restrict__ C, int K,
    const float* __restrict__ al, const float* __restrict__ ar,
    float* __restrict__ el, float* __restrict__ er)
{
    extern __shared__ uint32_t sm[];
    uint32_t* As = sm;                  // 2 x TILE_AW
    uint32_t* Bs = sm + 2 * TILE_AW;    // 2 x TILE_BW
    int tid = threadIdx.x;
    int lane = tid & 31, wid = tid >> 5;
    int wm = (wid & 1) * 64, wn = (wid >> 1) * 64;   // 2 x 4 warps
    int g = lane >> 2, tig = lane & 3;
    const __nv_bfloat16* Ab = A + (size_t)blockIdx.y * 128 * K;
    const __nv_bfloat16* Bb = Bt + (size_t)blockIdx.x * 256 * K;

    float c[4][8][4];
#pragma unroll
    for (int mt = 0; mt < 4; mt++)
#pragma unroll
        for (int nt = 0; nt < 8; nt++)
#pragma unroll
            for (int i = 0; i < 4; i++) c[mt][nt][i] = 0.f;

    bf16_load_tiles(As, Bs, Ab, Bb, 0, 0, tid, K);
    int nk = K / BK2;
    for (int t = 0; t < nk; t++) {
        int buf = t & 1;
        asm volatile("cp.async.wait_group 0;" ::: "memory");
        __syncthreads();
        if (t + 1 < nk)
            bf16_load_tiles(As, Bs, Ab, Bb, buf ^ 1, (t + 1) * BK2, tid, K);
        const uint32_t* A2 = As + buf * TILE_AW;
        const uint32_t* B2 = Bs + buf * TILE_BW;
#pragma unroll
        for (int kk2 = 0; kk2 < 2; kk2++) {
            int kw = kk2 * 8;
            unsigned a[4][4], b[8][2];
#pragma unroll
            for (int mt = 0; mt < 4; mt++) {
                int base = (wm + mt * 16 + g) * ROWW + kw + tig;
                a[mt][0] = A2[base];
                a[mt][1] = A2[base + 8 * ROWW];
                a[mt][2] = A2[base + 4];
                a[mt][3] = A2[base + 8 * ROWW + 4];
            }
#pragma unroll
            for (int nt = 0; nt < 8; nt++) {
                int base = (wn + nt * 8 + g) * ROWW + kw + tig;
                b[nt][0] = B2[base];
                b[nt][1] = B2[base + 4];
            }
#pragma unroll
            for (int mt = 0; mt < 4; mt++)
#pragma unroll
                for (int nt = 0; nt < 8; nt++)
                    asm volatile(
                        "mma.sync.aligned.m16n8k16.row.col.f32.bf16.bf16.f32 "
                        "{%0,%1,%2,%3}, {%4,%5,%6,%7}, {%8,%9}, {%0,%1,%2,%3};"
                        : "+f"(c[mt][nt][0]), "+f"(c[mt][nt][1]),
                          "+f"(c[mt][nt][2]), "+f"(c[mt][nt][3])
                        : "r"(a[mt][0]), "r"(a[mt][1]), "r"(a[mt][2]), "r"(a[mt][3]),
                          "r"(b[nt][0]), "r"(b[nt][1]));
        }
        __syncthreads();
    }

    // ---- epilogue: bf16 store + fused el/er partial dots ----
    __nv_bfloat16* Cb = C + (size_t)(blockIdx.y * 128) * NHD + blockIdx.x * 256;
    float pel[8], per[8];
#pragma unroll
    for (int i = 0; i < 8; i++) { pel[i] = 0.f; per[i] = 0.f; }
#pragma unroll
    for (int nt = 0; nt < 8; nt++) {
        int colg = blockIdx.x * 256 + wn + nt * 8 + 2 * tig;
        float a0 = al[colg], a1 = al[colg + 1];
        float r0 = ar[colg], r1 = ar[colg + 1];
#pragma unroll
        for (int mt = 0; mt < 4; mt++) {
            int row = wm + mt * 16 + g;
            int col = wn + nt * 8 + 2 * tig;
            *(__nv_bfloat162*)(Cb + (size_t)row * NHD + col) =
                __floats2bfloat162_rn(c[mt][nt][0], c[mt][nt][1]);
            *(__nv_bfloat162*)(Cb + (size_t)(row + 8) * NHD + col) =
                __floats2bfloat162_rn(c[mt][nt][2], c[mt][nt][3]);
            pel[mt * 2]     += c[mt][nt][0] * a0 + c[mt][nt][1] * a1;
            pel[mt * 2 + 1] += c[mt][nt][2] * a0 + c[mt][nt][3] * a1;
            per[mt * 2]     += c[mt][nt][0] * r0 + c[mt][nt][1] * r1;
            per[mt * 2 + 1] += c[mt][nt][2] * r0 + c[mt][nt][3] * r1;
        }
    }
    // reduce across the 4 tig lanes sharing each row
#pragma unroll
    for (int off = 1; off <= 2; off <<= 1)
#pragma unroll
        for (int i = 0; i < 8; i++) {
            pel[i] += __shfl_xor_sync(0xffffffffu, pel[i], off);
            per[i] += __shfl_xor_sync(0xffffffffu, per[i], off);
        }
    if (tig == 0) {
        int hd = (blockIdx.x * 256) / NF;   // 256-col tile never crosses heads (768=3*256)
#pragma unroll
        for (int mt = 0; mt < 4; mt++)
#pragma unroll
            for (int hf = 0; hf < 2; hf++) {
                int n = blockIdx.y * 128 + wm + mt * 16 + hf * 8 + g;
                atomicAdd(&el[n * NH + hd], pel[mt * 2 + hf]);
                atomicAdd(&er[n * NH + hd], per[mt * 2 + hf]);
            }
    }
}

// ---------------- fp32 -> bf16 convert ----------------
__global__ void cvt16_kernel(const float* __restrict__ x, __nv_bfloat16* __restrict__ o, int n) {
    int i = blockIdx.x * 256 + threadIdx.x;
    if (i < n) o[i] = __float2bfloat16(x[i]);
}

// ---------------- W[K][M] -> Bt[M][K] bf16 transpose ----------------
__global__ __launch_bounds__(256) void wtrans_kernel(
    const float* __restrict__ W, __nv_bfloat16* __restrict__ Bt, int K, int M)
{
    __shared__ float t[32][33];
    int m0 = blockIdx.x * 32, k0 = blockIdx.y * 32;
    int tx = threadIdx.x & 31, ty = threadIdx.x >> 5;  // 32 x 8
#pragma unroll
    for (int i = 0; i < 32; i += 8)
        t[ty + i][tx] = W[(size_t)(k0 + ty + i) * M + m0 + tx];
    __syncthreads();
#pragma unroll
    for (int i = 0; i < 32; i += 8)
        Bt[(size_t)(m0 + ty + i) * K + k0 + tx] = __float2bfloat16(t[tx][ty + i]);
}

// ---------------- per-layer zeroing (colsums + el/er) ----------------
__global__ void prep_kernel() {
    int i = blockIdx.x * 256 + threadIdx.x;
    if (i < NHD) { g_colsum[i] = 0.f; g_colsq[i] = 0.f; }
    if (i < NN * NH) { g_el[i] = 0.f; g_er[i] = 0.f; }
}

// ---------------- edge softmax + aggregation (+bias), bf16 feat/h ----------------
__global__ __launch_bounds__(256) void aggregate_kernel(
    const __nv_bfloat16* __restrict__ feat, const float* __restrict__ el,
    const float* __restrict__ er, const int* __restrict__ esrc,
    const float* __restrict__ bias, __nv_bfloat16* __restrict__ outh)
{
    int n = blockIdx.x;
    __shared__ int   ssrc[DEG];
    __shared__ float salpha[NH * DEG];
    int tid = threadIdx.x;
    if (tid < DEG) ssrc[tid] = esrc[n * DEG + tid];
    __syncthreads();
    if (tid < 32) {
        int h = tid >> 3, k = tid & 7;
        float e = el[ssrc[k] * NH + h] + er[n * NH + h];
        e = e > 0.f ? e : 0.2f * e;
        float m = e;
#pragma unroll
        for (int o = 4; o; o >>= 1) m = fmaxf(m, __shfl_xor_sync(0xffffffffu, m, o));
        float a = __expf(e - m);
        float s = a;
#pragma unroll
        for (int o = 4; o; o >>= 1) s += __shfl_xor_sync(0xffffffffu, s, o);
        salpha[tid] = a / s;
    }
    __syncthreads();
    const __nv_bfloat162* f2 = (const __nv_bfloat162*)feat;
    __nv_bfloat162* o2 = (__nv_bfloat162*)outh;
    for (int c2 = tid; c2 < NHD / 2; c2 += 256) {
        int h = c2 / (NF / 2);
        float accx = bias[2 * c2], accy = bias[2 * c2 + 1];
#pragma unroll
        for (int k = 0; k < DEG; k++) {
            float w = salpha[h * DEG + k];
            float2 v = __bfloat1622float2(f2[(size_t)ssrc[k] * (NHD / 2) + c2]);
            accx += w * v.x; accy += w * v.y;
        }
        o2[(size_t)n * (NHD / 2) + c2] = __floats2bfloat162_rn(accx, accy);
    }
}

// ---------------- column stats (LayerNorm over axis 0), bf16 input ----------------
__global__ __launch_bounds__(256) void colstats_kernel(const __nv_bfloat16* __restrict__ x) {
    int c2 = blockIdx.x * 256 + threadIdx.x;   // pair index
    int r0 = blockIdx.y * 256;
    const __nv_bfloat162* x2 = (const __nv_bfloat162*)x;
    float s0 = 0.f, s1 = 0.f, q0 = 0.f, q1 = 0.f;
    for (int r = r0; r < r0 + 256; r++) {
        float2 v = __bfloat1622float2(x2[(size_t)r * (NHD / 2) + c2]);
        s0 += v.x; q0 += v.x * v.x;
        s1 += v.y; q1 += v.y * v.y;
    }
    atomicAdd(&g_colsum[2 * c2], s0);
    atomicAdd(&g_colsum[2 * c2 + 1], s1);
    atomicAdd(&g_colsq[2 * c2], q0);
    atomicAdd(&g_colsq[2 * c2 + 1], q1);
}

__global__ void colfin_kernel(const float* __restrict__ gamma, const float* __restrict__ beta) {
    int c = blockIdx.x * 256 + threadIdx.x;
    if (c >= NHD) return;
    float mu  = g_colsum[c] * (1.f / NN);
    float var = g_colsq[c] * (1.f / NN) - mu * mu;
    float rs  = rsqrtf(var + 1e-5f);
    float a   = rs * gamma[c];
    g_colA[c] = a;
    g_colB[c] = beta[c] - mu * a;
}

// ---------------- LN + PReLU epilogues (fused bf16 convert / head-mean) ----------------
__global__ __launch_bounds__(256) void lnfuse1_kernel(
    const __nv_bfloat16* __restrict__ h, const float* __restrict__ pa,
    __nv_bfloat16* __restrict__ a16, float* __restrict__ m1)
{
    int n = blockIdx.x;
    for (int f = threadIdx.x; f < NF; f += 256) {
        float s = 0.f;
#pragma unroll
        for (int hh = 0; hh < 4; hh++) {
            int c = hh * NF + f;
            float y = g_colA[c] * __bfloat162float(h[(size_t)n * NHD + c]) + g_colB[c];
            y = y > 0.f ? y : pa[c] * y;
            a16[(size_t)n * NHD + c] = __float2bfloat16(y);
            s += y;
        }
        m1[(size_t)n * NF + f] = 0.25f * s;
    }
}

__global__ __launch_bounds__(256) void lnfuse2_kernel(
    const __nv_bfloat16* __restrict__ h, const float* __restrict__ pa)
{
    int n = blockIdx.x;
    for (int f = threadIdx.x; f < NF; f += 256) {
        float s = 0.f;
#pragma unroll
        for (int hh = 0; hh < 4; hh++) {
            int c = hh * NF + f;
            float y = g_colA[c] * __bfloat162float(h[(size_t)n * NHD + c]) + g_colB[c];
            y = y > 0.f ? y : pa[c] * y;
            s += y;
        }
        g_rep[(size_t)n * NF + f] = fmaxf(g_m1[(size_t)n * NF + f], 0.25f * s);
    }
}

// ---------------- sims: S[128 x 8192] = Qe @ rep^T ----------------
__global__ __launch_bounds__(256) void simgemm_kernel(
    const float* __restrict__ Qe, const float* __restrict__ R)
{
    __shared__ float Qs[128][33];
    __shared__ float Rs[32][33];
    int tid = threadIdx.x;
    int n0 = blockIdx.x * 32;
    float acc[16];
#pragma unroll
    for (int i = 0; i < 16; i++) acc[i] = 0.f;
    int n = tid & 31, rb = tid >> 5;

    for (int k0 = 0; k0 < ND; k0 += 32) {
#pragma unroll
        for (int t = 0; t < 16; t++) {
            int li = tid + t * 256;
            Qs[li >> 5][li & 31] = Qe[(size_t)(li >> 5) * ND + k0 + (li & 31)];
        }
#pragma unroll
        for (int t = 0; t < 4; t++) {
            int li = tid + t * 256;
            Rs[li >> 5][li & 31] = R[(size_t)(n0 + (li >> 5)) * ND + k0 + (li & 31)];
        }
        __syncthreads();
#pragma unroll
        for (int kk = 0; kk < 32; kk++) {
            float b = Rs[n][kk];
#pragma unroll
            for (int i = 0; i < 16; i++)
                acc[i] += Qs[rb + 8 * i][kk] * b;
        }
        __syncthreads();
    }
#pragma unroll
    for (int i = 0; i < 16; i++)
        g_S[(size_t)(rb + 8 * i) * NN + n0 + n] = acc[i];
}

// ---------------- output zero ----------------
__global__ void zeroout_kernel(float* out) {
    if (threadIdx.x < 3) out[threadIdx.x] = 0.f;
}

// ---------------- losses ----------------
__device__ __forceinline__ float warpSumF(float v) {
#pragma unroll
    for (int o = 16; o; o >>= 1) v += __shfl_xor_sync(0xffffffffu, v, o);
    return v;
}

__device__ __forceinline__ float blockSumF(float v, float* sred, int tid) {
    v = warpSumF(v);
    if ((tid & 31) == 0) sred[tid >> 5] = v;
    __syncthreads();
    if (tid < 32) {
        float x = (tid < 16) ? sred[tid] : 0.f;
        x = warpSumF(x);
        if (tid == 0) sred[0] = x;
    }
    __syncthreads();
    float r = sred[0];
    __syncthreads();
    return r;
}

__device__ __forceinline__ float blockMaxF(float v, float* sred, int tid) {
#pragma unroll
    for (int o = 16; o; o >>= 1) v = fmaxf(v, __shfl_xor_sync(0xffffffffu, v, o));
    if ((tid & 31) == 0) sred[tid >> 5] = v;
    __syncthreads();
    if (tid < 32) {
        float x = (tid < 16) ? sred[tid] : -INFINITY;
#pragma unroll
        for (int o = 16; o; o >>= 1) x = fmaxf(x, __shfl_xor_sync(0xffffffffu, x, o));
        if (tid == 0) sred[0] = x;
    }
    __syncthreads();
    float r = sred[0];
    __syncthreads();
    return r;
}

__device__ void bitonic1024_desc(float* key, int* idx, int tid) {
    for (int k = 2; k <= 1024; k <<= 1) {
        for (int j = k >> 1; j > 0; j >>= 1) {
#pragma unroll 1
            for (int t = tid; t < 1024; t += 512) {
                int x = t ^ j;
                if (x > t) {
                    bool descSeg = ((t & k) == 0);
                    float ka = key[t], kb = key[x];
                    int   ia = idx[t], ib = idx[x];
                    bool aFirst = (ka > kb) || (ka == kb && ia < ib);
                    bool doSwap = descSeg ? (!aFirst) : aFirst;
                    if (doSwap) { key[t] = kb; key[x] = ka; idx[t] = ib; idx[x] = ia; }
                }
            }
            __syncthreads();
        }
    }
}

__global__ __launch_bounds__(512) void loss_kernel(const float* __restrict__ bert, float* __restrict__ out) {
    __shared__ float skey[1024];
    __shared__ int   sidx[1024];
    __shared__ float sred[16];
    __shared__ float sh_psim;
    int r = blockIdx.x;
    int g = r >> 4;
    int base = g * NPG;
    int tid = threadIdx.x;
    const float* Srow = g_S + (size_t)r * NN;

    skey[tid]       = bert[(size_t)r * NPG + tid];       sidx[tid]       = tid;
    skey[tid + 512] = bert[(size_t)r * NPG + tid + 512]; sidx[tid + 512] = tid + 512;
    __syncthreads();
    bitonic1024_desc(skey, sidx, tid);

    int i0 = sidx[tid], i1 = sidx[tid + 512];
    float v0 = Srow[base + i0], v1 = Srow[base + i1];
    __syncthreads();
    skey[tid] = v0;       sidx[tid] = tid;
    skey[tid + 512] = v1; sidx[tid + 512] = tid + 512;
    if (tid == 0) sh_psim = v0;
    __syncthreads();

    bitonic1024_desc(skey, sidx, tid);

    float L = 0.f;
    for (int i = 0; i < 1023; i++) {
        float yi = skey[i];
        int   pi = sidx[i];
        for (int j = i + 1 + tid; j < 1024; j += 512) {
            float s = yi - skey[j];
            float t = fminf(s, 50.f);
            float u = __logf(1.f + __expf(-t));
            L += u + ((pi > sidx[j]) ? t : 0.f);
        }
    }
    float Ltot = blockSumF(L, sred, tid);

    float mx = -INFINITY;
    for (int c = tid; c < NN; c += 512) mx = fmaxf(mx, Srow[c]);
    float m = blockMaxF(mx, sred, tid);

    float se = 0.f, s1 = 0.f, s2 = 0.f;
    for (int c = tid; c < NN; c += 512) {
        float x = Srow[c] - m;
        float e = __expf(x);
        se += e;
        if (c >= base && c < base + NPG) { s1 += e; s2 += x * e; }
    }
    se = blockSumF(se, sred, tid);
    s1 = blockSumF(s1, sred, tid);
    s2 = blockSumF(s2, sred, tid);

    if (tid == 0) {
        float lse = m + __logf(se);
        float cl  = lse - sh_psim;
        float ent = __logf(s1) - s2 / s1;
        atomicAdd(out + 0, cl  * (1.f / 128.f));
        atomicAdd(out + 2, ent * (1.f / 128.f));
        atomicAdd(out + 1, Ltot * (1.f / 67043328.f));
    }
}

// ---------------- launch ----------------
extern "C" void kernel_launch(void* const* d_in, const int* in_sizes, int n_in,
                              void* d_out, int out_size) {
    const float* x      = (const float*)d_in[0];
    const int*   esrc   = (const int*)d_in[1];
    const float* qe     = (const float*)d_in[3];
    const float* bert   = (const float*)d_in[4];
    const float* W1     = (const float*)d_in[5];
    const float* al1    = (const float*)d_in[6];
    const float* ar1    = (const float*)d_in[7];
    const float* b1     = (const float*)d_in[8];
    const float* gamma1 = (const float*)d_in[9];
    const float* beta1  = (const float*)d_in[10];
    const float* pa1    = (const float*)d_in[11];
    const float* W2     = (const float*)d_in[12];
    const float* al2    = (const float*)d_in[13];
    const float* ar2    = (const float*)d_in[14];
    const float* b2     = (const float*)d_in[15];
    const float* gamma2 = (const float*)d_in[16];
    const float* beta2  = (const float*)d_in[17];
    const float* pa2    = (const float*)d_in[18];
    float* out = (float*)d_out;

    float *el, *er, *m1, *rep;
    __nv_bfloat16 *feat16, *h16, *a16, *bT;
    cudaGetSymbolAddress((void**)&feat16, g_feat16);
    cudaGetSymbolAddress((void**)&h16,    g_h16);
    cudaGetSymbolAddress((void**)&el,     g_el);
    cudaGetSymbolAddress((void**)&er,     g_er);
    cudaGetSymbolAddress((void**)&m1,     g_m1);
    cudaGetSymbolAddress((void**)&rep,    g_rep);
    cudaGetSymbolAddress((void**)&a16,    g_a16);
    cudaGetSymbolAddress((void**)&bT,     g_bT);

    cudaFuncSetAttribute(bf16_gemm_kernel,
                         cudaFuncAttributeMaxDynamicSharedMemorySize, GEMM_SMEM);

    dim3 gGemm(NHD / 256, NN / 128);       // (12, 64)
    dim3 gStats(NHD / 512, NN / 256);      // (6, 32)

    zeroout_kernel<<<1, 32>>>(out);

    // ---- layer 1 ----
    cvt16_kernel<<<(NN * ND + 255) / 256, 256>>>(x, a16, NN * ND);
    wtrans_kernel<<<dim3(NHD / 32, ND / 32), 256>>>(W1, bT, ND, NHD);
    prep_kernel<<<(NN * NH + 255) / 256, 256>>>();
    bf16_gemm_kernel<<<gGemm, 256, GEMM_SMEM>>>(a16, bT, feat16, ND, al1, ar1, el, er);
    aggregate_kernel<<<NN, 256>>>(feat16, el, er, esrc, b1, h16);
    colstats_kernel<<<gStats, 256>>>(h16);
    colfin_kernel<<<NHD / 256, 256>>>(gamma1, beta1);
    lnfuse1_kernel<<<NN, 256>>>(h16, pa1, a16, m1);

    // ---- layer 2 ----
    wtrans_kernel<<<dim3(NHD / 32, NHD / 32), 256>>>(W2, bT, NHD, NHD);
    prep_kernel<<<(NN * NH + 255) / 256, 256>>>();
    bf16_gemm_kernel<<<gGemm, 256, GEMM_SMEM>>>(a16, bT, feat16, NHD, al2, ar2, el, er);
    aggregate_kernel<<<NN, 256>>>(feat16, el, er, esrc, b2, h16);
    colstats_kernel<<<gStats, 256>>>(h16);
    colfin_kernel<<<NHD / 256, 256>>>(gamma2, beta2);
    lnfuse2_kernel<<<NN, 256>>>(h16, pa2);

    // ---- similarities + losses ----
    simgemm_kernel<<<NN / 32, 256>>>(qe, rep);
    loss_kernel<<<NROW, 512>>>(bert, out);
}

// round 9
// speedup vs baseline: 1.5239x; 1.0901x over previous
#include <cuda_runtime.h>
#include <cuda_bf16.h>
#include <math.h>
#include <stdint.h>

#define NN   8192
#define DEG  8
#define NH   4
#define NF   768
#define NHD  3072
#define ND   768
#define NBG  8
#define NPG  1024
#define NQ   16
#define NROW 128   // NBG*NQ

// ---------------- scratch (static device memory; no allocation) ----------------
__device__ __nv_bfloat16 g_feat16[(size_t)NN * NHD]; // GEMM output (feat), bf16
__device__ __nv_bfloat16 g_h16[(size_t)NN * NHD];    // aggregate output (pre-LN), bf16
__device__ __nv_bfloat16 g_a16[(size_t)NN * NHD];    // bf16 GEMM A operand
__device__ __nv_bfloat16 g_bT[(size_t)NHD * NHD];    // bf16 transposed weights [M][K]
__device__ float g_el[NN * NH];
__device__ float g_er[NN * NH];
__device__ float g_m1[(size_t)NN * NF];
__device__ float g_rep[(size_t)NN * NF];
__device__ float g_S[(size_t)NROW * NN];
__device__ float g_colsum[NHD];
__device__ float g_colsq[NHD];
__device__ float g_colA[NHD];
__device__ float g_colB[NHD];

// ================= bf16 tensor-core GEMM (mma.sync m16n8k16) =================
// 256 threads = 8 warps (2x4), block tile 128x256x32, warp tile 64x64.
// Fused epilogue: el/er partial dots + atomicAdd.
#define BK2   32
#define ROWW  20                     // 32-bit words per smem row
#define TILE_AW (128 * ROWW)
#define TILE_BW (256 * ROWW)
#define GEMM_SMEM ((2 * TILE_AW + 2 * TILE_BW) * 4)   // 60KB

__device__ __forceinline__ void cp_async16(void* dst, const void* src) {
    unsigned int s = (unsigned int)__cvta_generic_to_shared(dst);
    asm volatile("cp.async.cg.shared.global [%0], [%1], 16;" :: "r"(s), "l"(src));
}

__device__ __forceinline__ void bf16_load_tiles(
    uint32_t* As, uint32_t* Bs, const __nv_bfloat16* Ab, const __nv_bfloat16* Bb,
    int buf, int k0, int tid, int K)
{
#pragma unroll
    for (int i = 0; i < 2; i++) {
        int li = tid + i * 256;
        int r = li >> 2, ch = li & 3;
        cp_async16((char*)(As + buf * TILE_AW) + r * 80 + ch * 16,
                   Ab + (size_t)r * K + k0 + ch * 8);
    }
#pragma unroll
    for (int i = 0; i < 4; i++) {
        int li = tid + i * 256;
        int r = li >> 2, ch = li & 3;
        cp_async16((char*)(Bs + buf * TILE_BW) + r * 80 + ch * 16,
                   Bb + (size_t)r * K + k0 + ch * 8);
    }
    asm volatile("cp.async.commit_group;");
}

__global__ __launch_bounds__(256) void bf16_gemm_kernel(
    const __nv_bfloat16* __restrict__ A, const __nv_bfloat16* __restrict__ Bt,
    __nv_bfloat16* __restrict__ C, int K,
    const float* __restrict__ al, const float* __restrict__ ar,
    float* __restrict__ el, float* __restrict__ er)
{
    extern __shared__ uint32_t sm[];
    uint32_t* As = sm;
    uint32_t* Bs = sm + 2 * TILE_AW;
    int tid = threadIdx.x;
    int lane = tid & 31, wid = tid >> 5;
    int wm = (wid & 1) * 64, wn = (wid >> 1) * 64;
    int g = lane >> 2, tig = lane & 3;
    const __nv_bfloat16* Ab = A + (size_t)blockIdx.y * 128 * K;
    const __nv_bfloat16* Bb = Bt + (size_t)blockIdx.x * 256 * K;

    float c[4][8][4];
#pragma unroll
    for (int mt = 0; mt < 4; mt++)
#pragma unroll
        for (int nt = 0; nt < 8; nt++)
#pragma unroll
            for (int i = 0; i < 4; i++) c[mt][nt][i] = 0.f;

    bf16_load_tiles(As, Bs, Ab, Bb, 0, 0, tid, K);
    int nk = K / BK2;
    for (int t = 0; t < nk; t++) {
        int buf = t & 1;
        asm volatile("cp.async.wait_group 0;" ::: "memory");
        __syncthreads();
        if (t + 1 < nk)
            bf16_load_tiles(As, Bs, Ab, Bb, buf ^ 1, (t + 1) * BK2, tid, K);
        const uint32_t* A2 = As + buf * TILE_AW;
        const uint32_t* B2 = Bs + buf * TILE_BW;
#pragma unroll
        for (int kk2 = 0; kk2 < 2; kk2++) {
            int kw = kk2 * 8;
            unsigned a[4][4], b[8][2];
#pragma unroll
            for (int mt = 0; mt < 4; mt++) {
                int base = (wm + mt * 16 + g) * ROWW + kw + tig;
                a[mt][0] = A2[base];
                a[mt][1] = A2[base + 8 * ROWW];
                a[mt][2] = A2[base + 4];
                a[mt][3] = A2[base + 8 * ROWW + 4];
            }
#pragma unroll
            for (int nt = 0; nt < 8; nt++) {
                int base = (wn + nt * 8 + g) * ROWW + kw + tig;
                b[nt][0] = B2[base];
                b[nt][1] = B2[base + 4];
            }
#pragma unroll
            for (int mt = 0; mt < 4; mt++)
#pragma unroll
                for (int nt = 0; nt < 8; nt++)
                    asm volatile(
                        "mma.sync.aligned.m16n8k16.row.col.f32.bf16.bf16.f32 "
                        "{%0,%1,%2,%3}, {%4,%5,%6,%7}, {%8,%9}, {%0,%1,%2,%3};"
                        : "+f"(c[mt][nt][0]), "+f"(c[mt][nt][1]),
                          "+f"(c[mt][nt][2]), "+f"(c[mt][nt][3])
                        : "r"(a[mt][0]), "r"(a[mt][1]), "r"(a[mt][2]), "r"(a[mt][3]),
                          "r"(b[nt][0]), "r"(b[nt][1]));
        }
        __syncthreads();
    }

    __nv_bfloat16* Cb = C + (size_t)(blockIdx.y * 128) * NHD + blockIdx.x * 256;
    float pel[8], per[8];
#pragma unroll
    for (int i = 0; i < 8; i++) { pel[i] = 0.f; per[i] = 0.f; }
#pragma unroll
    for (int nt = 0; nt < 8; nt++) {
        int colg = blockIdx.x * 256 + wn + nt * 8 + 2 * tig;
        float a0 = al[colg], a1 = al[colg + 1];
        float r0 = ar[colg], r1 = ar[colg + 1];
#pragma unroll
        for (int mt = 0; mt < 4; mt++) {
            int row = wm + mt * 16 + g;
            int col = wn + nt * 8 + 2 * tig;
            *(__nv_bfloat162*)(Cb + (size_t)row * NHD + col) =
                __floats2bfloat162_rn(c[mt][nt][0], c[mt][nt][1]);
            *(__nv_bfloat162*)(Cb + (size_t)(row + 8) * NHD + col) =
                __floats2bfloat162_rn(c[mt][nt][2], c[mt][nt][3]);
            pel[mt * 2]     += c[mt][nt][0] * a0 + c[mt][nt][1] * a1;
            pel[mt * 2 + 1] += c[mt][nt][2] * a0 + c[mt][nt][3] * a1;
            per[mt * 2]     += c[mt][nt][0] * r0 + c[mt][nt][1] * r1;
            per[mt * 2 + 1] += c[mt][nt][2] * r0 + c[mt][nt][3] * r1;
        }
    }
#pragma unroll
    for (int off = 1; off <= 2; off <<= 1)
#pragma unroll
        for (int i = 0; i < 8; i++) {
            pel[i] += __shfl_xor_sync(0xffffffffu, pel[i], off);
            per[i] += __shfl_xor_sync(0xffffffffu, per[i], off);
        }
    if (tig == 0) {
        int hd = (blockIdx.x * 256) / NF;
#pragma unroll
        for (int mt = 0; mt < 4; mt++)
#pragma unroll
            for (int hf = 0; hf < 2; hf++) {
                int n = blockIdx.y * 128 + wm + mt * 16 + hf * 8 + g;
                atomicAdd(&el[n * NH + hd], pel[mt * 2 + hf]);
                atomicAdd(&er[n * NH + hd], per[mt * 2 + hf]);
            }
    }
}

// ---------------- fp32 -> bf16 convert ----------------
__global__ void cvt16_kernel(const float* __restrict__ x, __nv_bfloat16* __restrict__ o, int n) {
    int i = blockIdx.x * 256 + threadIdx.x;
    if (i < n) o[i] = __float2bfloat16(x[i]);
}

// ---------------- W[K][M] -> Bt[M][K] bf16 transpose ----------------
__global__ __launch_bounds__(256) void wtrans_kernel(
    const float* __restrict__ W, __nv_bfloat16* __restrict__ Bt, int K, int M)
{
    __shared__ float t[32][33];
    int m0 = blockIdx.x * 32, k0 = blockIdx.y * 32;
    int tx = threadIdx.x & 31, ty = threadIdx.x >> 5;
#pragma unroll
    for (int i = 0; i < 32; i += 8)
        t[ty + i][tx] = W[(size_t)(k0 + ty + i) * M + m0 + tx];
    __syncthreads();
#pragma unroll
    for (int i = 0; i < 32; i += 8)
        Bt[(size_t)(m0 + ty + i) * K + k0 + tx] = __float2bfloat16(t[tx][ty + i]);
}

// ---------------- per-layer zeroing ----------------
__global__ void prep_kernel() {
    int i = blockIdx.x * 256 + threadIdx.x;
    if (i < NHD) { g_colsum[i] = 0.f; g_colsq[i] = 0.f; }
    if (i < NN * NH) { g_el[i] = 0.f; g_er[i] = 0.f; }
}

// ---------------- edge softmax + aggregation (+bias), bf16 ----------------
__global__ __launch_bounds__(256) void aggregate_kernel(
    const __nv_bfloat16* __restrict__ feat, const float* __restrict__ el,
    const float* __restrict__ er, const int* __restrict__ esrc,
    const float* __restrict__ bias, __nv_bfloat16* __restrict__ outh)
{
    int n = blockIdx.x;
    __shared__ int   ssrc[DEG];
    __shared__ float salpha[NH * DEG];
    int tid = threadIdx.x;
    if (tid < DEG) ssrc[tid] = esrc[n * DEG + tid];
    __syncthreads();
    if (tid < 32) {
        int h = tid >> 3, k = tid & 7;
        float e = el[ssrc[k] * NH + h] + er[n * NH + h];
        e = e > 0.f ? e : 0.2f * e;
        float m = e;
#pragma unroll
        for (int o = 4; o; o >>= 1) m = fmaxf(m, __shfl_xor_sync(0xffffffffu, m, o));
        float a = __expf(e - m);
        float s = a;
#pragma unroll
        for (int o = 4; o; o >>= 1) s += __shfl_xor_sync(0xffffffffu, s, o);
        salpha[tid] = a / s;
    }
    __syncthreads();
    const __nv_bfloat162* f2 = (const __nv_bfloat162*)feat;
    __nv_bfloat162* o2 = (__nv_bfloat162*)outh;
    for (int c2 = tid; c2 < NHD / 2; c2 += 256) {
        int h = c2 / (NF / 2);
        float accx = bias[2 * c2], accy = bias[2 * c2 + 1];
#pragma unroll
        for (int k = 0; k < DEG; k++) {
            float w = salpha[h * DEG + k];
            float2 v = __bfloat1622float2(f2[(size_t)ssrc[k] * (NHD / 2) + c2]);
            accx += w * v.x; accy += w * v.y;
        }
        o2[(size_t)n * (NHD / 2) + c2] = __floats2bfloat162_rn(accx, accy);
    }
}

// ---------------- column stats ----------------
__global__ __launch_bounds__(256) void colstats_kernel(const __nv_bfloat16* __restrict__ x) {
    int c2 = blockIdx.x * 256 + threadIdx.x;
    int r0 = blockIdx.y * 256;
    const __nv_bfloat162* x2 = (const __nv_bfloat162*)x;
    float s0 = 0.f, s1 = 0.f, q0 = 0.f, q1 = 0.f;
    for (int r = r0; r < r0 + 256; r++) {
        float2 v = __bfloat1622float2(x2[(size_t)r * (NHD / 2) + c2]);
        s0 += v.x; q0 += v.x * v.x;
        s1 += v.y; q1 += v.y * v.y;
    }
    atomicAdd(&g_colsum[2 * c2], s0);
    atomicAdd(&g_colsum[2 * c2 + 1], s1);
    atomicAdd(&g_colsq[2 * c2], q0);
    atomicAdd(&g_colsq[2 * c2 + 1], q1);
}

__global__ void colfin_kernel(const float* __restrict__ gamma, const float* __restrict__ beta) {
    int c = blockIdx.x * 256 + threadIdx.x;
    if (c >= NHD) return;
    float mu  = g_colsum[c] * (1.f / NN);
    float var = g_colsq[c] * (1.f / NN) - mu * mu;
    float rs  = rsqrtf(var + 1e-5f);
    float a   = rs * gamma[c];
    g_colA[c] = a;
    g_colB[c] = beta[c] - mu * a;
}

// ---------------- LN + PReLU epilogues ----------------
__global__ __launch_bounds__(256) void lnfuse1_kernel(
    const __nv_bfloat16* __restrict__ h, const float* __restrict__ pa,
    __nv_bfloat16* __restrict__ a16, float* __restrict__ m1)
{
    int n = blockIdx.x;
    for (int f = threadIdx.x; f < NF; f += 256) {
        float s = 0.f;
#pragma unroll
        for (int hh = 0; hh < 4; hh++) {
            int c = hh * NF + f;
            float y = g_colA[c] * __bfloat162float(h[(size_t)n * NHD + c]) + g_colB[c];
            y = y > 0.f ? y : pa[c] * y;
            a16[(size_t)n * NHD + c] = __float2bfloat16(y);
            s += y;
        }
        m1[(size_t)n * NF + f] = 0.25f * s;
    }
}

__global__ __launch_bounds__(256) void lnfuse2_kernel(
    const __nv_bfloat16* __restrict__ h, const float* __restrict__ pa)
{
    int n = blockIdx.x;
    for (int f = threadIdx.x; f < NF; f += 256) {
        float s = 0.f;
#pragma unroll
        for (int hh = 0; hh < 4; hh++) {
            int c = hh * NF + f;
            float y = g_colA[c] * __bfloat162float(h[(size_t)n * NHD + c]) + g_colB[c];
            y = y > 0.f ? y : pa[c] * y;
            s += y;
        }
        g_rep[(size_t)n * NF + f] = fmaxf(g_m1[(size_t)n * NF + f], 0.25f * s);
    }
}

// ---------------- sims: S[128 x 8192] = Qe @ rep^T ----------------
__global__ __launch_bounds__(256) void simgemm_kernel(
    const float* __restrict__ Qe, const float* __restrict__ R)
{
    __shared__ float Qs[128][33];
    __shared__ float Rs[32][33];
    int tid = threadIdx.x;
    int n0 = blockIdx.x * 32;
    float acc[16];
#pragma unroll
    for (int i = 0; i < 16; i++) acc[i] = 0.f;
    int n = tid & 31, rb = tid >> 5;

    for (int k0 = 0; k0 < ND; k0 += 32) {
#pragma unroll
        for (int t = 0; t < 16; t++) {
            int li = tid + t * 256;
            Qs[li >> 5][li & 31] = Qe[(size_t)(li >> 5) * ND + k0 + (li & 31)];
        }
#pragma unroll
        for (int t = 0; t < 4; t++) {
            int li = tid + t * 256;
            Rs[li >> 5][li & 31] = R[(size_t)(n0 + (li >> 5)) * ND + k0 + (li & 31)];
        }
        __syncthreads();
#pragma unroll
        for (int kk = 0; kk < 32; kk++) {
            float b = Rs[n][kk];
#pragma unroll
            for (int i = 0; i < 16; i++)
                acc[i] += Qs[rb + 8 * i][kk] * b;
        }
        __syncthreads();
    }
#pragma unroll
    for (int i = 0; i < 16; i++)
        g_S[(size_t)(rb + 8 * i) * NN + n0 + n] = acc[i];
}

// ---------------- output zero ----------------
__global__ void zeroout_kernel(float* out) {
    if (threadIdx.x < 3) out[threadIdx.x] = 0.f;
}

// ---------------- losses ----------------
__device__ __forceinline__ float warpSumF(float v) {
#pragma unroll
    for (int o = 16; o; o >>= 1) v += __shfl_xor_sync(0xffffffffu, v, o);
    return v;
}

__device__ __forceinline__ float blockSumF(float v, float* sred, int tid) {
    v = warpSumF(v);
    if ((tid & 31) == 0) sred[tid >> 5] = v;
    __syncthreads();
    if (tid < 32) {
        float x = (tid < 16) ? sred[tid] : 0.f;
        x = warpSumF(x);
        if (tid == 0) sred[0] = x;
    }
    __syncthreads();
    float r = sred[0];
    __syncthreads();
    return r;
}

__device__ __forceinline__ float blockMaxF(float v, float* sred, int tid) {
#pragma unroll
    for (int o = 16; o; o >>= 1) v = fmaxf(v, __shfl_xor_sync(0xffffffffu, v, o));
    if ((tid & 31) == 0) sred[tid >> 5] = v;
    __syncthreads();
    if (tid < 32) {
        float x = (tid < 16) ? sred[tid] : -INFINITY;
#pragma unroll
        for (int o = 16; o; o >>= 1) x = fmaxf(x, __shfl_xor_sync(0xffffffffu, x, o));
        if (tid == 0) sred[0] = x;
    }
    __syncthreads();
    float r = sred[0];
    __syncthreads();
    return r;
}

__device__ void bitonic1024_desc(float* key, int* idx, int tid) {
    for (int k = 2; k <= 1024; k <<= 1) {
        for (int j = k >> 1; j > 0; j >>= 1) {
#pragma unroll 1
            for (int t = tid; t < 1024; t += 512) {
                int x = t ^ j;
                if (x > t) {
                    bool descSeg = ((t & k) == 0);
                    float ka = key[t], kb = key[x];
                    int   ia = idx[t], ib = idx[x];
                    bool aFirst = (ka > kb) || (ka == kb && ia < ib);
                    bool doSwap = descSeg ? (!aFirst) : aFirst;
                    if (doSwap) { key[t] = kb; key[x] = ka; idx[t] = ib; idx[x] = ia; }
                }
            }
            __syncthreads();
        }
    }
}

// lambda-MRR via product trick: sum_{i<j} log1p(e^{-(yi-yj)}) = sum_i log prod_j (1 + ez_j/ez_i)
// plus masked t-part sum_{i<j, pi>pj} min(yi-yj, 50). No per-pair MUFU.
__global__ __launch_bounds__(512) void loss_kernel(const float* __restrict__ bert, float* __restrict__ out) {
    __shared__ float skey[1024];
    __shared__ int   sidx[1024];
    __shared__ float sez[1024];
    __shared__ float sred[16];
    __shared__ float sh_psim;
    int r = blockIdx.x;
    int g = r >> 4;
    int base = g * NPG;
    int tid = threadIdx.x;
    const float* Srow = g_S + (size_t)r * NN;

    // 1) sort bert scores descending -> order
    skey[tid]       = bert[(size_t)r * NPG + tid];       sidx[tid]       = tid;
    skey[tid + 512] = bert[(size_t)r * NPG + tid + 512]; sidx[tid + 512] = tid + 512;
    __syncthreads();
    bitonic1024_desc(skey, sidx, tid);

    // 2) gather sims in bert order; payload becomes bert rank
    int i0 = sidx[tid], i1 = sidx[tid + 512];
    float v0 = Srow[base + i0], v1 = Srow[base + i1];
    __syncthreads();
    skey[tid] = v0;       sidx[tid] = tid;
    skey[tid + 512] = v1; sidx[tid + 512] = tid + 512;
    if (tid == 0) sh_psim = v0;
    __syncthreads();

    // 3) sort by predicted sim descending (payload = bert rank)
    bitonic1024_desc(skey, sidx, tid);

    // 4) precompute ez_j = e^{y_j - y_0} in (0, 1]
    {
        float y0 = skey[0];
        sez[tid]       = __expf(fmaxf(skey[tid]       - y0, -60.f));
        sez[tid + 512] = __expf(fmaxf(skey[tid + 512] - y0, -60.f));
    }
    __syncthreads();

    // 5) pairwise loop: warp handles 32 i's (lane = i), broadcast-j inner loop.
    int wid = tid >> 5, lane = tid & 31;
    float uacc = 0.f, tacc = 0.f;
#pragma unroll 1
    for (int half = 0; half < 2; half++) {
        int c = half ? (31 - wid) : wid;
        int i = c * 32 + lane;
        float yi = skey[i];
        int   pi = sidx[i];
        float inv = __fdividef(1.f, sez[i]);
        float ts0 = 0.f, ts1 = 0.f, ts2 = 0.f, ts3 = 0.f;
#pragma unroll 1
        for (int jb = c * 32; jb < 1024; jb += 32) {
            float p0 = 1.f, p1 = 1.f, p2 = 1.f, p3 = 1.f;
#pragma unroll
            for (int q4 = 0; q4 < 8; q4++) {
                int j4 = jb + q4 * 4;
                float4 y4 = *(const float4*)&skey[j4];
                float4 e4 = *(const float4*)&sez[j4];
                int4   p4 = *(const int4*)&sidx[j4];
                {   bool act = (j4 + 0) > i;
                    p0 *= act ? fmaf(e4.x, inv, 1.f) : 1.f;
                    float t = fminf(yi - y4.x, 50.f);
                    if (act && pi > p4.x) ts0 += t; }
                {   bool act = (j4 + 1) > i;
                    p1 *= act ? fmaf(e4.y, inv, 1.f) : 1.f;
                    float t = fminf(yi - y4.y, 50.f);
                    if (act && pi > p4.y) ts1 += t; }
                {   bool act = (j4 + 2) > i;
                    p2 *= act ? fmaf(e4.z, inv, 1.f) : 1.f;
                    float t = fminf(yi - y4.z, 50.f);
                    if (act && pi > p4.z) ts2 += t; }
                {   bool act = (j4 + 3) > i;
                    p3 *= act ? fmaf(e4.w, inv, 1.f) : 1.f;
                    float t = fminf(yi - y4.w, 50.f);
                    if (act && pi > p4.w) ts3 += t; }
            }
            uacc += __logf((p0 * p1) * (p2 * p3));   // each p <= 2^8, product <= 2^32
        }
        tacc += (ts0 + ts1) + (ts2 + ts3);
    }
    float Ltot = blockSumF(uacc + tacc, sred, tid);

    // 6) row-wide logsumexp (cl) and own-segment entropy
    float mx = -INFINITY;
    for (int c = tid; c < NN; c += 512) mx = fmaxf(mx, Srow[c]);
    float m = blockMaxF(mx, sred, tid);

    float se = 0.f, s1 = 0.f, s2 = 0.f;
    for (int c = tid; c < NN; c += 512) {
        float x = Srow[c] - m;
        float e = __expf(x);
        se += e;
        if (c >= base && c < base + NPG) { s1 += e; s2 += x * e; }
    }
    se = blockSumF(se, sred, tid);
    s1 = blockSumF(s1, sred, tid);
    s2 = blockSumF(s2, sred, tid);

    if (tid == 0) {
        float lse = m + __logf(se);
        float cl  = lse - sh_psim;
        float ent = __logf(s1) - s2 / s1;
        atomicAdd(out + 0, cl  * (1.f / 128.f));
        atomicAdd(out + 2, ent * (1.f / 128.f));
        atomicAdd(out + 1, Ltot * (1.f / 67043328.f));
    }
}

// ---------------- launch ----------------
extern "C" void kernel_launch(void* const* d_in, const int* in_sizes, int n_in,
                              void* d_out, int out_size) {
    const float* x      = (const float*)d_in[0];
    const int*   esrc   = (const int*)d_in[1];
    const float* qe     = (const float*)d_in[3];
    const float* bert   = (const float*)d_in[4];
    const float* W1     = (const float*)d_in[5];
    const float* al1    = (const float*)d_in[6];
    const float* ar1    = (const float*)d_in[7];
    const float* b1     = (const float*)d_in[8];
    const float* gamma1 = (const float*)d_in[9];
    const float* beta1  = (const float*)d_in[10];
    const float* pa1    = (const float*)d_in[11];
    const float* W2     = (const float*)d_in[12];
    const float* al2    = (const float*)d_in[13];
    const float* ar2    = (const float*)d_in[14];
    const float* b2     = (const float*)d_in[15];
    const float* gamma2 = (const float*)d_in[16];
    const float* beta2  = (const float*)d_in[17];
    const float* pa2    = (const float*)d_in[18];
    float* out = (float*)d_out;

    float *el, *er, *m1, *rep;
    __nv_bfloat16 *feat16, *h16, *a16, *bT;
    cudaGetSymbolAddress((void**)&feat16, g_feat16);
    cudaGetSymbolAddress((void**)&h16,    g_h16);
    cudaGetSymbolAddress((void**)&el,     g_el);
    cudaGetSymbolAddress((void**)&er,     g_er);
    cudaGetSymbolAddress((void**)&m1,     g_m1);
    cudaGetSymbolAddress((void**)&rep,    g_rep);
    cudaGetSymbolAddress((void**)&a16,    g_a16);
    cudaGetSymbolAddress((void**)&bT,     g_bT);

    cudaFuncSetAttribute(bf16_gemm_kernel,
                         cudaFuncAttributeMaxDynamicSharedMemorySize, GEMM_SMEM);

    dim3 gGemm(NHD / 256, NN / 128);       // (12, 64)
    dim3 gStats(NHD / 512, NN / 256);      // (6, 32)

    zeroout_kernel<<<1, 32>>>(out);

    // ---- layer 1 ----
    cvt16_kernel<<<(NN * ND + 255) / 256, 256>>>(x, a16, NN * ND);
    wtrans_kernel<<<dim3(NHD / 32, ND / 32), 256>>>(W1, bT, ND, NHD);
    prep_kernel<<<(NN * NH + 255) / 256, 256>>>();
    bf16_gemm_kernel<<<gGemm, 256, GEMM_SMEM>>>(a16, bT, feat16, ND, al1, ar1, el, er);
    aggregate_kernel<<<NN, 256>>>(feat16, el, er, esrc, b1, h16);
    colstats_kernel<<<gStats, 256>>>(h16);
    colfin_kernel<<<NHD / 256, 256>>>(gamma1, beta1);
    lnfuse1_kernel<<<NN, 256>>>(h16, pa1, a16, m1);

    // ---- layer 2 ----
    wtrans_kernel<<<dim3(NHD / 32, NHD / 32), 256>>>(W2, bT, NHD, NHD);
    prep_kernel<<<(NN * NH + 255) / 256, 256>>>();
    bf16_gemm_kernel<<<gGemm, 256, GEMM_SMEM>>>(a16, bT, feat16, NHD, al2, ar2, el, er);
    aggregate_kernel<<<NN, 256>>>(feat16, el, er, esrc, b2, h16);
    colstats_kernel<<<gStats, 256>>>(h16);
    colfin_kernel<<<NHD / 256, 256>>>(gamma2, beta2);
    lnfuse2_kernel<<<NN, 256>>>(h16, pa2);

    // ---- similarities + losses ----
    simgemm_kernel<<<NN / 32, 256>>>(qe, rep);
    loss_kernel<<<NROW, 512>>>(bert, out);
}

// round 10
// speedup vs baseline: 1.7857x; 1.1718x over previous
#include <cuda_runtime.h>
#include <cuda_bf16.h>
#include <math.h>
#include <stdint.h>

#define NN   8192
#define DEG  8
#define NH   4
#define NF   768
#define NHD  3072
#define ND   768
#define NBG  8
#define NPG  1024
#define NQ   16
#define NROW 128   // NBG*NQ

// ---------------- scratch (static device memory; no allocation) ----------------
__device__ __nv_bfloat16 g_feat16[(size_t)NN * NHD]; // GEMM output (feat), bf16
__device__ __nv_bfloat16 g_h16[(size_t)NN * NHD];    // aggregate output (pre-LN), bf16
__device__ __nv_bfloat16 g_a16[(size_t)NN * NHD];    // bf16 GEMM A operand
__device__ __nv_bfloat16 g_bT[(size_t)NHD * NHD];    // bf16 transposed weights [M][K]
__device__ float g_el[NN * NH];
__device__ float g_er[NN * NH];
__device__ float g_m1[(size_t)NN * NF];
__device__ float g_rep[(size_t)NN * NF];
__device__ float g_S[(size_t)NROW * NN];
__device__ float g_colsum[NHD];
__device__ float g_colsq[NHD];
__device__ float g_colA[NHD];
__device__ float g_colB[NHD];

// ================= bf16 tensor-core GEMM (mma.sync m16n8k16 + ldmatrix) =================
// C[N x 3072] = A[N x K](bf16) @ Bt[3072 x K]^T(bf16), fp32 accum, bf16 out.
// 256 threads = 8 warps (2m x 4n), block tile 128x128x32, warp tile 64x32.
// <=128 regs/thread (launch_bounds 256,2) -> 2 CTAs/SM = 16 warps/SM.
// Fragments loaded with ldmatrix.x4 (conflict-free with ROWW=20 padding).
// Fused epilogue: el/er partial dots + atomicAdd.
#define BK2   32
#define ROWW  20                     // 32-bit words per smem row (80 B)
#define TILE_W (128 * ROWW)
#define GEMM_SMEM (4 * TILE_W * 4)   // A+B x double buffer = 40 KB

__device__ __forceinline__ void cp_async16(void* dst, const void* src) {
    unsigned int s = (unsigned int)__cvta_generic_to_shared(dst);
    asm volatile("cp.async.cg.shared.global [%0], [%1], 16;" :: "r"(s), "l"(src));
}

#define LDSM4(r0, r1, r2, r3, addr) \
    asm volatile("ldmatrix.sync.aligned.m8n8.x4.shared.b16 {%0,%1,%2,%3}, [%4];" \
        : "=r"(r0), "=r"(r1), "=r"(r2), "=r"(r3) : "r"(addr))

__device__ __forceinline__ void bf16_load_tiles(
    uint32_t* As, uint32_t* Bs, const __nv_bfloat16* Ab, const __nv_bfloat16* Bb,
    int buf, int k0, int tid, int K)
{
#pragma unroll
    for (int i = 0; i < 2; i++) {
        int li = tid + i * 256;          // 0..511
        int r = li >> 2, ch = li & 3;    // 128 rows x 4 16B-chunks
        cp_async16((char*)(As + buf * TILE_W) + r * 80 + ch * 16,
                   Ab + (size_t)r * K + k0 + ch * 8);
    }
#pragma unroll
    for (int i = 0; i < 2; i++) {
        int li = tid + i * 256;
        int r = li >> 2, ch = li & 3;
        cp_async16((char*)(Bs + buf * TILE_W) + r * 80 + ch * 16,
                   Bb + (size_t)r * K + k0 + ch * 8);
    }
    asm volatile("cp.async.commit_group;");
}

__global__ void __launch_bounds__(256, 2) bf16_gemm_kernel(
    const __nv_bfloat16* __restrict__ A, const __nv_bfloat16* __restrict__ Bt,
    __nv_bfloat16* __restrict__ C, int K,
    const float* __restrict__ al, const float* __restrict__ ar,
    float* __restrict__ el, float* __restrict__ er)
{
    extern __shared__ uint32_t sm[];
    uint32_t* As = sm;                  // 2 x TILE_W
    uint32_t* Bs = sm + 2 * TILE_W;     // 2 x TILE_W
    int tid = threadIdx.x;
    int lane = tid & 31, wid = tid >> 5;
    int wm = (wid & 1) * 64, wn = (wid >> 1) * 32;
    int g = lane >> 2, tig = lane & 3;
    const __nv_bfloat16* Ab = A + (size_t)blockIdx.y * 128 * K;
    const __nv_bfloat16* Bb = Bt + (size_t)blockIdx.x * 128 * K;

    unsigned sAb = (unsigned)__cvta_generic_to_shared(As);
    unsigned sBb = (unsigned)__cvta_generic_to_shared(Bs);
    // per-thread ldmatrix base offsets (bytes)
    unsigned aoff = (unsigned)((wm + (lane & 15)) * 80 + (lane >> 4) * 16);
    unsigned boff = (unsigned)((wn + ((lane >> 4) & 1) * 8 + (lane & 7)) * 80
                               + ((lane >> 3) & 1) * 16);

    float c[4][4][4];
#pragma unroll
    for (int mt = 0; mt < 4; mt++)
#pragma unroll
        for (int nt = 0; nt < 4; nt++)
#pragma unroll
            for (int i = 0; i < 4; i++) c[mt][nt][i] = 0.f;

    bf16_load_tiles(As, Bs, Ab, Bb, 0, 0, tid, K);
    int nk = K / BK2;
    for (int t = 0; t < nk; t++) {
        int buf = t & 1;
        asm volatile("cp.async.wait_group 0;" ::: "memory");
        __syncthreads();
        if (t + 1 < nk)
            bf16_load_tiles(As, Bs, Ab, Bb, buf ^ 1, (t + 1) * BK2, tid, K);
        unsigned sa = sAb + (unsigned)(buf * TILE_W * 4);
        unsigned sb = sBb + (unsigned)(buf * TILE_W * 4);
#pragma unroll
        for (int kk2 = 0; kk2 < 2; kk2++) {
            unsigned a[4][4], b[4][2];
#pragma unroll
            for (int mt = 0; mt < 4; mt++)
                LDSM4(a[mt][0], a[mt][1], a[mt][2], a[mt][3],
                      sa + aoff + (unsigned)(mt * 16 * 80 + kk2 * 32));
#pragma unroll
            for (int ntp = 0; ntp < 2; ntp++)
                LDSM4(b[ntp * 2][0], b[ntp * 2][1], b[ntp * 2 + 1][0], b[ntp * 2 + 1][1],
                      sb + boff + (unsigned)(ntp * 16 * 80 + kk2 * 32));
#pragma unroll
            for (int mt = 0; mt < 4; mt++)
#pragma unroll
                for (int nt = 0; nt < 4; nt++)
                    asm volatile(
                        "mma.sync.aligned.m16n8k16.row.col.f32.bf16.bf16.f32 "
                        "{%0,%1,%2,%3}, {%4,%5,%6,%7}, {%8,%9}, {%0,%1,%2,%3};"
                        : "+f"(c[mt][nt][0]), "+f"(c[mt][nt][1]),
                          "+f"(c[mt][nt][2]), "+f"(c[mt][nt][3])
                        : "r"(a[mt][0]), "r"(a[mt][1]), "r"(a[mt][2]), "r"(a[mt][3]),
                          "r"(b[nt][0]), "r"(b[nt][1]));
        }
        __syncthreads();
    }

    // ---- epilogue: bf16 store + fused el/er partial dots ----
    __nv_bfloat16* Cb = C + (size_t)(blockIdx.y * 128) * NHD + blockIdx.x * 128;
    float pel[8], per[8];
#pragma unroll
    for (int i = 0; i < 8; i++) { pel[i] = 0.f; per[i] = 0.f; }
#pragma unroll
    for (int nt = 0; nt < 4; nt++) {
        int colg = blockIdx.x * 128 + wn + nt * 8 + 2 * tig;
        float a0 = al[colg], a1 = al[colg + 1];
        float r0 = ar[colg], r1 = ar[colg + 1];
#pragma unroll
        for (int mt = 0; mt < 4; mt++) {
            int row = wm + mt * 16 + g;
            int col = wn + nt * 8 + 2 * tig;
            *(__nv_bfloat162*)(Cb + (size_t)row * NHD + col) =
                __floats2bfloat162_rn(c[mt][nt][0], c[mt][nt][1]);
            *(__nv_bfloat162*)(Cb + (size_t)(row + 8) * NHD + col) =
                __floats2bfloat162_rn(c[mt][nt][2], c[mt][nt][3]);
            pel[mt * 2]     += c[mt][nt][0] * a0 + c[mt][nt][1] * a1;
            pel[mt * 2 + 1] += c[mt][nt][2] * a0 + c[mt][nt][3] * a1;
            per[mt * 2]     += c[mt][nt][0] * r0 + c[mt][nt][1] * r1;
            per[mt * 2 + 1] += c[mt][nt][2] * r0 + c[mt][nt][3] * r1;
        }
    }
#pragma unroll
    for (int off = 1; off <= 2; off <<= 1)
#pragma unroll
        for (int i = 0; i < 8; i++) {
            pel[i] += __shfl_xor_sync(0xffffffffu, pel[i], off);
            per[i] += __shfl_xor_sync(0xffffffffu, per[i], off);
        }
    if (tig == 0) {
        int hd = (blockIdx.x * 128) / NF;   // 128-col tile never crosses heads
#pragma unroll
        for (int mt = 0; mt < 4; mt++)
#pragma unroll
            for (int hf = 0; hf < 2; hf++) {
                int n = blockIdx.y * 128 + wm + mt * 16 + hf * 8 + g;
                atomicAdd(&el[n * NH + hd], pel[mt * 2 + hf]);
                atomicAdd(&er[n * NH + hd], per[mt * 2 + hf]);
            }
    }
}

// ---------------- fp32 -> bf16 convert ----------------
__global__ void cvt16_kernel(const float* __restrict__ x, __nv_bfloat16* __restrict__ o, int n) {
    int i = blockIdx.x * 256 + threadIdx.x;
    if (i < n) o[i] = __float2bfloat16(x[i]);
}

// ---------------- W[K][M] -> Bt[M][K] bf16 transpose ----------------
__global__ __launch_bounds__(256) void wtrans_kernel(
    const float* __restrict__ W, __nv_bfloat16* __restrict__ Bt, int K, int M)
{
    __shared__ float t[32][33];
    int m0 = blockIdx.x * 32, k0 = blockIdx.y * 32;
    int tx = threadIdx.x & 31, ty = threadIdx.x >> 5;
#pragma unroll
    for (int i = 0; i < 32; i += 8)
        t[ty + i][tx] = W[(size_t)(k0 + ty + i) * M + m0 + tx];
    __syncthreads();
#pragma unroll
    for (int i = 0; i < 32; i += 8)
        Bt[(size_t)(m0 + ty + i) * K + k0 + tx] = __float2bfloat16(t[tx][ty + i]);
}

// ---------------- per-layer zeroing ----------------
__global__ void prep_kernel() {
    int i = blockIdx.x * 256 + threadIdx.x;
    if (i < NHD) { g_colsum[i] = 0.f; g_colsq[i] = 0.f; }
    if (i < NN * NH) { g_el[i] = 0.f; g_er[i] = 0.f; }
}

// ---------------- edge softmax + aggregation (+bias), bf16 ----------------
__global__ __launch_bounds__(256) void aggregate_kernel(
    const __nv_bfloat16* __restrict__ feat, const float* __restrict__ el,
    const float* __restrict__ er, const int* __restrict__ esrc,
    const float* __restrict__ bias, __nv_bfloat16* __restrict__ outh)
{
    int n = blockIdx.x;
    __shared__ int   ssrc[DEG];
    __shared__ float salpha[NH * DEG];
    int tid = threadIdx.x;
    if (tid < DEG) ssrc[tid] = esrc[n * DEG + tid];
    __syncthreads();
    if (tid < 32) {
        int h = tid >> 3, k = tid & 7;
        float e = el[ssrc[k] * NH + h] + er[n * NH + h];
        e = e > 0.f ? e : 0.2f * e;
        float m = e;
#pragma unroll
        for (int o = 4; o; o >>= 1) m = fmaxf(m, __shfl_xor_sync(0xffffffffu, m, o));
        float a = __expf(e - m);
        float s = a;
#pragma unroll
        for (int o = 4; o; o >>= 1) s += __shfl_xor_sync(0xffffffffu, s, o);
        salpha[tid] = a / s;
    }
    __syncthreads();
    const __nv_bfloat162* f2 = (const __nv_bfloat162*)feat;
    __nv_bfloat162* o2 = (__nv_bfloat162*)outh;
    for (int c2 = tid; c2 < NHD / 2; c2 += 256) {
        int h = c2 / (NF / 2);
        float accx = bias[2 * c2], accy = bias[2 * c2 + 1];
#pragma unroll
        for (int k = 0; k < DEG; k++) {
            float w = salpha[h * DEG + k];
            float2 v = __bfloat1622float2(f2[(size_t)ssrc[k] * (NHD / 2) + c2]);
            accx += w * v.x; accy += w * v.y;
        }
        o2[(size_t)n * (NHD / 2) + c2] = __floats2bfloat162_rn(accx, accy);
    }
}

// ---------------- column stats ----------------
__global__ __launch_bounds__(256) void colstats_kernel(const __nv_bfloat16* __restrict__ x) {
    int c2 = blockIdx.x * 256 + threadIdx.x;
    int r0 = blockIdx.y * 256;
    const __nv_bfloat162* x2 = (const __nv_bfloat162*)x;
    float s0 = 0.f, s1 = 0.f, q0 = 0.f, q1 = 0.f;
    for (int r = r0; r < r0 + 256; r++) {
        float2 v = __bfloat1622float2(x2[(size_t)r * (NHD / 2) + c2]);
        s0 += v.x; q0 += v.x * v.x;
        s1 += v.y; q1 += v.y * v.y;
    }
    atomicAdd(&g_colsum[2 * c2], s0);
    atomicAdd(&g_colsum[2 * c2 + 1], s1);
    atomicAdd(&g_colsq[2 * c2], q0);
    atomicAdd(&g_colsq[2 * c2 + 1], q1);
}

__global__ void colfin_kernel(const float* __restrict__ gamma, const float* __restrict__ beta) {
    int c = blockIdx.x * 256 + threadIdx.x;
    if (c >= NHD) return;
    float mu  = g_colsum[c] * (1.f / NN);
    float var = g_colsq[c] * (1.f / NN) - mu * mu;
    float rs  = rsqrtf(var + 1e-5f);
    float a   = rs * gamma[c];
    g_colA[c] = a;
    g_colB[c] = beta[c] - mu * a;
}

// ---------------- LN + PReLU epilogues ----------------
__global__ __launch_bounds__(256) void lnfuse1_kernel(
    const __nv_bfloat16* __restrict__ h, const float* __restrict__ pa,
    __nv_bfloat16* __restrict__ a16, float* __restrict__ m1)
{
    int n = blockIdx.x;
    for (int f = threadIdx.x; f < NF; f += 256) {
        float s = 0.f;
#pragma unroll
        for (int hh = 0; hh < 4; hh++) {
            int c = hh * NF + f;
            float y = g_colA[c] * __bfloat162float(h[(size_t)n * NHD + c]) + g_colB[c];
            y = y > 0.f ? y : pa[c] * y;
            a16[(size_t)n * NHD + c] = __float2bfloat16(y);
            s += y;
        }
        m1[(size_t)n * NF + f] = 0.25f * s;
    }
}

__global__ __launch_bounds__(256) void lnfuse2_kernel(
    const __nv_bfloat16* __restrict__ h, const float* __restrict__ pa)
{
    int n = blockIdx.x;
    for (int f = threadIdx.x; f < NF; f += 256) {
        float s = 0.f;
#pragma unroll
        for (int hh = 0; hh < 4; hh++) {
            int c = hh * NF + f;
            float y = g_colA[c] * __bfloat162float(h[(size_t)n * NHD + c]) + g_colB[c];
            y = y > 0.f ? y : pa[c] * y;
            s += y;
        }
        g_rep[(size_t)n * NF + f] = fmaxf(g_m1[(size_t)n * NF + f], 0.25f * s);
    }
}

// ---------------- sims: S[128 x 8192] = Qe @ rep^T ----------------
__global__ __launch_bounds__(256) void simgemm_kernel(
    const float* __restrict__ Qe, const float* __restrict__ R)
{
    __shared__ float Qs[128][33];
    __shared__ float Rs[32][33];
    int tid = threadIdx.x;
    int n0 = blockIdx.x * 32;
    float acc[16];
#pragma unroll
    for (int i = 0; i < 16; i++) acc[i] = 0.f;
    int n = tid & 31, rb = tid >> 5;

    for (int k0 = 0; k0 < ND; k0 += 32) {
#pragma unroll
        for (int t = 0; t < 16; t++) {
            int li = tid + t * 256;
            Qs[li >> 5][li & 31] = Qe[(size_t)(li >> 5) * ND + k0 + (li & 31)];
        }
#pragma unroll
        for (int t = 0; t < 4; t++) {
            int li = tid + t * 256;
            Rs[li >> 5][li & 31] = R[(size_t)(n0 + (li >> 5)) * ND + k0 + (li & 31)];
        }
        __syncthreads();
#pragma unroll
        for (int kk = 0; kk < 32; kk++) {
            float b = Rs[n][kk];
#pragma unroll
            for (int i = 0; i < 16; i++)
                acc[i] += Qs[rb + 8 * i][kk] * b;
        }
        __syncthreads();
    }
#pragma unroll
    for (int i = 0; i < 16; i++)
        g_S[(size_t)(rb + 8 * i) * NN + n0 + n] = acc[i];
}

// ---------------- output zero ----------------
__global__ void zeroout_kernel(float* out) {
    if (threadIdx.x < 3) out[threadIdx.x] = 0.f;
}

// ---------------- losses ----------------
__device__ __forceinline__ float warpSumF(float v) {
#pragma unroll
    for (int o = 16; o; o >>= 1) v += __shfl_xor_sync(0xffffffffu, v, o);
    return v;
}

__device__ __forceinline__ float blockSumF(float v, float* sred, int tid) {
    v = warpSumF(v);
    if ((tid & 31) == 0) sred[tid >> 5] = v;
    __syncthreads();
    if (tid < 32) {
        float x = (tid < 16) ? sred[tid] : 0.f;
        x = warpSumF(x);
        if (tid == 0) sred[0] = x;
    }
    __syncthreads();
    float r = sred[0];
    __syncthreads();
    return r;
}

__device__ __forceinline__ float blockMaxF(float v, float* sred, int tid) {
#pragma unroll
    for (int o = 16; o; o >>= 1) v = fmaxf(v, __shfl_xor_sync(0xffffffffu, v, o));
    if ((tid & 31) == 0) sred[tid >> 5] = v;
    __syncthreads();
    if (tid < 32) {
        float x = (tid < 16) ? sred[tid] : -INFINITY;
#pragma unroll
        for (int o = 16; o; o >>= 1) x = fmaxf(x, __shfl_xor_sync(0xffffffffu, x, o));
        if (tid == 0) sred[0] = x;
    }
    __syncthreads();
    float r = sred[0];
    __syncthreads();
    return r;
}

__device__ void bitonic1024_desc(float* key, int* idx, int tid) {
    for (int k = 2; k <= 1024; k <<= 1) {
        for (int j = k >> 1; j > 0; j >>= 1) {
#pragma unroll 1
            for (int t = tid; t < 1024; t += 512) {
                int x = t ^ j;
                if (x > t) {
                    bool descSeg = ((t & k) == 0);
                    float ka = key[t], kb = key[x];
                    int   ia = idx[t], ib = idx[x];
                    bool aFirst = (ka > kb) || (ka == kb && ia < ib);
                    bool doSwap = descSeg ? (!aFirst) : aFirst;
                    if (doSwap) { key[t] = kb; key[x] = ka; idx[t] = ib; idx[x] = ia; }
                }
            }
            __syncthreads();
        }
    }
}

// lambda-MRR via product trick: sum_{i<j} log1p(e^{-(yi-yj)}) = sum_i log prod_j (1 + ez_j/ez_i)
// plus masked t-part sum_{i<j, pi>pj} min(yi-yj, 50). No per-pair MUFU.
__global__ __launch_bounds__(512) void loss_kernel(const float* __restrict__ bert, float* __restrict__ out) {
    __shared__ float skey[1024];
    __shared__ int   sidx[1024];
    __shared__ float sez[1024];
    __shared__ float sred[16];
    __shared__ float sh_psim;
    int r = blockIdx.x;
    int g = r >> 4;
    int base = g * NPG;
    int tid = threadIdx.x;
    const float* Srow = g_S + (size_t)r * NN;

    skey[tid]       = bert[(size_t)r * NPG + tid];       sidx[tid]       = tid;
    skey[tid + 512] = bert[(size_t)r * NPG + tid + 512]; sidx[tid + 512] = tid + 512;
    __syncthreads();
    bitonic1024_desc(skey, sidx, tid);

    int i0 = sidx[tid], i1 = sidx[tid + 512];
    float v0 = Srow[base + i0], v1 = Srow[base + i1];
    __syncthreads();
    skey[tid] = v0;       sidx[tid] = tid;
    skey[tid + 512] = v1; sidx[tid + 512] = tid + 512;
    if (tid == 0) sh_psim = v0;
    __syncthreads();

    bitonic1024_desc(skey, sidx, tid);

    {
        float y0 = skey[0];
        sez[tid]       = __expf(fmaxf(skey[tid]       - y0, -60.f));
        sez[tid + 512] = __expf(fmaxf(skey[tid + 512] - y0, -60.f));
    }
    __syncthreads();

    int wid = tid >> 5, lane = tid & 31;
    float uacc = 0.f, tacc = 0.f;
#pragma unroll 1
    for (int half = 0; half < 2; half++) {
        int c = half ? (31 - wid) : wid;
        int i = c * 32 + lane;
        float yi = skey[i];
        int   pi = sidx[i];
        float inv = __fdividef(1.f, sez[i]);
        float ts0 = 0.f, ts1 = 0.f, ts2 = 0.f, ts3 = 0.f;
#pragma unroll 1
        for (int jb = c * 32; jb < 1024; jb += 32) {
            float p0 = 1.f, p1 = 1.f, p2 = 1.f, p3 = 1.f;
#pragma unroll
            for (int q4 = 0; q4 < 8; q4++) {
                int j4 = jb + q4 * 4;
                float4 y4 = *(const float4*)&skey[j4];
                float4 e4 = *(const float4*)&sez[j4];
                int4   p4 = *(const int4*)&sidx[j4];
                {   bool act = (j4 + 0) > i;
                    p0 *= act ? fmaf(e4.x, inv, 1.f) : 1.f;
                    float t = fminf(yi - y4.x, 50.f);
                    if (act && pi > p4.x) ts0 += t; }
                {   bool act = (j4 + 1) > i;
                    p1 *= act ? fmaf(e4.y, inv, 1.f) : 1.f;
                    float t = fminf(yi - y4.y, 50.f);
                    if (act && pi > p4.y) ts1 += t; }
                {   bool act = (j4 + 2) > i;
                    p2 *= act ? fmaf(e4.z, inv, 1.f) : 1.f;
                    float t = fminf(yi - y4.z, 50.f);
                    if (act && pi > p4.z) ts2 += t; }
                {   bool act = (j4 + 3) > i;
                    p3 *= act ? fmaf(e4.w, inv, 1.f) : 1.f;
                    float t = fminf(yi - y4.w, 50.f);
                    if (act && pi > p4.w) ts3 += t; }
            }
            uacc += __logf((p0 * p1) * (p2 * p3));
        }
        tacc += (ts0 + ts1) + (ts2 + ts3);
    }
    float Ltot = blockSumF(uacc + tacc, sred, tid);

    float mx = -INFINITY;
    for (int c = tid; c < NN; c += 512) mx = fmaxf(mx, Srow[c]);
    float m = blockMaxF(mx, sred, tid);

    float se = 0.f, s1 = 0.f, s2 = 0.f;
    for (int c = tid; c < NN; c += 512) {
        float x = Srow[c] - m;
        float e = __expf(x);
        se += e;
        if (c >= base && c < base + NPG) { s1 += e; s2 += x * e; }
    }
    se = blockSumF(se, sred, tid);
    s1 = blockSumF(s1, sred, tid);
    s2 = blockSumF(s2, sred, tid);

    if (tid == 0) {
        float lse = m + __logf(se);
        float cl  = lse - sh_psim;
        float ent = __logf(s1) - s2 / s1;
        atomicAdd(out + 0, cl  * (1.f / 128.f));
        atomicAdd(out + 2, ent * (1.f / 128.f));
        atomicAdd(out + 1, Ltot * (1.f / 67043328.f));
    }
}

// ---------------- launch ----------------
extern "C" void kernel_launch(void* const* d_in, const int* in_sizes, int n_in,
                              void* d_out, int out_size) {
    const float* x      = (const float*)d_in[0];
    const int*   esrc   = (const int*)d_in[1];
    const float* qe     = (const float*)d_in[3];
    const float* bert   = (const float*)d_in[4];
    const float* W1     = (const float*)d_in[5];
    const float* al1    = (const float*)d_in[6];
    const float* ar1    = (const float*)d_in[7];
    const float* b1     = (const float*)d_in[8];
    const float* gamma1 = (const float*)d_in[9];
    const float* beta1  = (const float*)d_in[10];
    const float* pa1    = (const float*)d_in[11];
    const float* W2     = (const float*)d_in[12];
    const float* al2    = (const float*)d_in[13];
    const float* ar2    = (const float*)d_in[14];
    const float* b2     = (const float*)d_in[15];
    const float* gamma2 = (const float*)d_in[16];
    const float* beta2  = (const float*)d_in[17];
    const float* pa2    = (const float*)d_in[18];
    float* out = (float*)d_out;

    float *el, *er, *m1, *rep;
    __nv_bfloat16 *feat16, *h16, *a16, *bT;
    cudaGetSymbolAddress((void**)&feat16, g_feat16);
    cudaGetSymbolAddress((void**)&h16,    g_h16);
    cudaGetSymbolAddress((void**)&el,     g_el);
    cudaGetSymbolAddress((void**)&er,     g_er);
    cudaGetSymbolAddress((void**)&m1,     g_m1);
    cudaGetSymbolAddress((void**)&rep,    g_rep);
    cudaGetSymbolAddress((void**)&a16,    g_a16);
    cudaGetSymbolAddress((void**)&bT,     g_bT);

    cudaFuncSetAttribute(bf16_gemm_kernel,
                         cudaFuncAttributeMaxDynamicSharedMemorySize, GEMM_SMEM);

    dim3 gGemm(NHD / 128, NN / 128);       // (24, 64)
    dim3 gStats(NHD / 512, NN / 256);      // (6, 32)

    zeroout_kernel<<<1, 32>>>(out);

    // ---- layer 1 ----
    cvt16_kernel<<<(NN * ND + 255) / 256, 256>>>(x, a16, NN * ND);
    wtrans_kernel<<<dim3(NHD / 32, ND / 32), 256>>>(W1, bT, ND, NHD);
    prep_kernel<<<(NN * NH + 255) / 256, 256>>>();
    bf16_gemm_kernel<<<gGemm, 256, GEMM_SMEM>>>(a16, bT, feat16, ND, al1, ar1, el, er);
    aggregate_kernel<<<NN, 256>>>(feat16, el, er, esrc, b1, h16);
    colstats_kernel<<<gStats, 256>>>(h16);
    colfin_kernel<<<NHD / 256, 256>>>(gamma1, beta1);
    lnfuse1_kernel<<<NN, 256>>>(h16, pa1, a16, m1);

    // ---- layer 2 ----
    wtrans_kernel<<<dim3(NHD / 32, NHD / 32), 256>>>(W2, bT, NHD, NHD);
    prep_kernel<<<(NN * NH + 255) / 256, 256>>>();
    bf16_gemm_kernel<<<gGemm, 256, GEMM_SMEM>>>(a16, bT, feat16, NHD, al2, ar2, el, er);
    aggregate_kernel<<<NN, 256>>>(feat16, el, er, esrc, b2, h16);
    colstats_kernel<<<gStats, 256>>>(h16);
    colfin_kernel<<<NHD / 256, 256>>>(gamma2, beta2);
    lnfuse2_kernel<<<NN, 256>>>(h16, pa2);

    // ---- similarities + losses ----
    simgemm_kernel<<<NN / 32, 256>>>(qe, rep);
    loss_kernel<<<NROW, 512>>>(bert, out);
}

// round 11
// speedup vs baseline: 1.9389x; 1.0858x over previous
#include <cuda_runtime.h>
#include <cuda_bf16.h>
#include <cuda_fp8.h>
#include <math.h>
#include <stdint.h>

#define NN   8192
#define DEG  8
#define NH   4
#define NF   768
#define NHD  3072
#define ND   768
#define NBG  8
#define NPG  1024
#define NQ   16
#define NROW 128   // NBG*NQ

// ---------------- scratch (static device memory; no allocation) ----------------
__device__ __nv_bfloat16 g_feat16[(size_t)NN * NHD]; // GEMM output (feat), bf16
__device__ __nv_bfloat16 g_h16[(size_t)NN * NHD];    // aggregate output (pre-LN), bf16
__device__ __nv_fp8_e4m3 g_a8[(size_t)NN * NHD];     // fp8 GEMM A operand
__device__ __nv_fp8_e4m3 g_bT8[(size_t)NHD * NHD];   // fp8 transposed weights [M][K]
__device__ float g_el[NN * NH];
__device__ float g_er[NN * NH];
__device__ float g_m1[(size_t)NN * NF];
__device__ float g_rep[(size_t)NN * NF];
__device__ float g_S[(size_t)NROW * NN];
__device__ float g_colsum[NHD];
__device__ float g_colsq[NHD];
__device__ float g_colA[NHD];
__device__ float g_colB[NHD];

// ================= fp8 tensor-core GEMM (mma.sync m16n8k32 e4m3 + ldmatrix) =========
// C[N x 3072] = A[N x K](e4m3) @ Bt[3072 x K]^T(e4m3), fp32 accum, bf16 out.
// 256 threads = 8 warps (2m x 4n), block tile 128x128x64(fp8), warp tile 64x32.
// Fragment layout of m16n8k32.e4m3 == m16n8k16.bf16 with 2 fp8 per b16 ->
// identical smem layout (80B rows), identical ldmatrix offsets (conflict-free).
// <=128 regs (launch_bounds 256,2) -> 2 CTAs/SM. Fused el/er epilogue.
#define BK8   64                     // fp8 elements per K-tile (64 B data/row)
#define ROWW  20                     // 32-bit words per smem row (80 B)
#define TILE_W (128 * ROWW)
#define GEMM_SMEM (4 * TILE_W * 4)   // A+B x double buffer = 40 KB

__device__ __forceinline__ void cp_async16(void* dst, const void* src) {
    unsigned int s = (unsigned int)__cvta_generic_to_shared(dst);
    asm volatile("cp.async.cg.shared.global [%0], [%1], 16;" :: "r"(s), "l"(src));
}

#define LDSM4(r0, r1, r2, r3, addr) \
    asm volatile("ldmatrix.sync.aligned.m8n8.x4.shared.b16 {%0,%1,%2,%3}, [%4];" \
        : "=r"(r0), "=r"(r1), "=r"(r2), "=r"(r3) : "r"(addr))

__device__ __forceinline__ void fp8_load_tiles(
    uint32_t* As, uint32_t* Bs, const __nv_fp8_e4m3* Ab, const __nv_fp8_e4m3* Bb,
    int buf, int k0, int tid, int K)
{
#pragma unroll
    for (int i = 0; i < 2; i++) {
        int li = tid + i * 256;          // 0..511
        int r = li >> 2, ch = li & 3;    // 128 rows x 4 16B-chunks (64 fp8)
        cp_async16((char*)(As + buf * TILE_W) + r * 80 + ch * 16,
                   Ab + (size_t)r * K + k0 + ch * 16);
    }
#pragma unroll
    for (int i = 0; i < 2; i++) {
        int li = tid + i * 256;
        int r = li >> 2, ch = li & 3;
        cp_async16((char*)(Bs + buf * TILE_W) + r * 80 + ch * 16,
                   Bb + (size_t)r * K + k0 + ch * 16);
    }
    asm volatile("cp.async.commit_group;");
}

__global__ void __launch_bounds__(256, 2) fp8_gemm_kernel(
    const __nv_fp8_e4m3* __restrict__ A, const __nv_fp8_e4m3* __restrict__ Bt,
    __nv_bfloat16* __restrict__ C, int K,
    const float* __restrict__ al, const float* __restrict__ ar,
    float* __restrict__ el, float* __restrict__ er)
{
    extern __shared__ uint32_t sm[];
    uint32_t* As = sm;                  // 2 x TILE_W
    uint32_t* Bs = sm + 2 * TILE_W;     // 2 x TILE_W
    int tid = threadIdx.x;
    int lane = tid & 31, wid = tid >> 5;
    int wm = (wid & 1) * 64, wn = (wid >> 1) * 32;
    int g = lane >> 2, tig = lane & 3;
    const __nv_fp8_e4m3* Ab = A + (size_t)blockIdx.y * 128 * K;
    const __nv_fp8_e4m3* Bb = Bt + (size_t)blockIdx.x * 128 * K;

    unsigned sAb = (unsigned)__cvta_generic_to_shared(As);
    unsigned sBb = (unsigned)__cvta_generic_to_shared(Bs);
    unsigned aoff = (unsigned)((wm + (lane & 15)) * 80 + (lane >> 4) * 16);
    unsigned boff = (unsigned)((wn + ((lane >> 4) & 1) * 8 + (lane & 7)) * 80
                               + ((lane >> 3) & 1) * 16);

    float c[4][4][4];
#pragma unroll
    for (int mt = 0; mt < 4; mt++)
#pragma unroll
        for (int nt = 0; nt < 4; nt++)
#pragma unroll
            for (int i = 0; i < 4; i++) c[mt][nt][i] = 0.f;

    fp8_load_tiles(As, Bs, Ab, Bb, 0, 0, tid, K);
    int nk = K / BK8;
    for (int t = 0; t < nk; t++) {
        int buf = t & 1;
        asm volatile("cp.async.wait_group 0;" ::: "memory");
        __syncthreads();
        if (t + 1 < nk)
            fp8_load_tiles(As, Bs, Ab, Bb, buf ^ 1, (t + 1) * BK8, tid, K);
        unsigned sa = sAb + (unsigned)(buf * TILE_W * 4);
        unsigned sb = sBb + (unsigned)(buf * TILE_W * 4);
#pragma unroll
        for (int kk2 = 0; kk2 < 2; kk2++) {          // 2 x k32 per 64-fp8 tile
            unsigned a[4][4], b[4][2];
#pragma unroll
            for (int mt = 0; mt < 4; mt++)
                LDSM4(a[mt][0], a[mt][1], a[mt][2], a[mt][3],
                      sa + aoff + (unsigned)(mt * 16 * 80 + kk2 * 32));
#pragma unroll
            for (int ntp = 0; ntp < 2; ntp++)
                LDSM4(b[ntp * 2][0], b[ntp * 2][1], b[ntp * 2 + 1][0], b[ntp * 2 + 1][1],
                      sb + boff + (unsigned)(ntp * 16 * 80 + kk2 * 32));
#pragma unroll
            for (int mt = 0; mt < 4; mt++)
#pragma unroll
                for (int nt = 0; nt < 4; nt++)
                    asm volatile(
                        "mma.sync.aligned.m16n8k32.row.col.f32.e4m3.e4m3.f32 "
                        "{%0,%1,%2,%3}, {%4,%5,%6,%7}, {%8,%9}, {%0,%1,%2,%3};"
                        : "+f"(c[mt][nt][0]), "+f"(c[mt][nt][1]),
                          "+f"(c[mt][nt][2]), "+f"(c[mt][nt][3])
                        : "r"(a[mt][0]), "r"(a[mt][1]), "r"(a[mt][2]), "r"(a[mt][3]),
                          "r"(b[nt][0]), "r"(b[nt][1]));
        }
        __syncthreads();
    }

    // ---- epilogue: bf16 store + fused el/er partial dots ----
    __nv_bfloat16* Cb = C + (size_t)(blockIdx.y * 128) * NHD + blockIdx.x * 128;
    float pel[8], per[8];
#pragma unroll
    for (int i = 0; i < 8; i++) { pel[i] = 0.f; per[i] = 0.f; }
#pragma unroll
    for (int nt = 0; nt < 4; nt++) {
        int colg = blockIdx.x * 128 + wn + nt * 8 + 2 * tig;
        float a0 = al[colg], a1 = al[colg + 1];
        float r0 = ar[colg], r1 = ar[colg + 1];
#pragma unroll
        for (int mt = 0; mt < 4; mt++) {
            int row = wm + mt * 16 + g;
            int col = wn + nt * 8 + 2 * tig;
            *(__nv_bfloat162*)(Cb + (size_t)row * NHD + col) =
                __floats2bfloat162_rn(c[mt][nt][0], c[mt][nt][1]);
            *(__nv_bfloat162*)(Cb + (size_t)(row + 8) * NHD + col) =
                __floats2bfloat162_rn(c[mt][nt][2], c[mt][nt][3]);
            pel[mt * 2]     += c[mt][nt][0] * a0 + c[mt][nt][1] * a1;
            pel[mt * 2 + 1] += c[mt][nt][2] * a0 + c[mt][nt][3] * a1;
            per[mt * 2]     += c[mt][nt][0] * r0 + c[mt][nt][1] * r1;
            per[mt * 2 + 1] += c[mt][nt][2] * r0 + c[mt][nt][3] * r1;
        }
    }
#pragma unroll
    for (int off = 1; off <= 2; off <<= 1)
#pragma unroll
        for (int i = 0; i < 8; i++) {
            pel[i] += __shfl_xor_sync(0xffffffffu, pel[i], off);
            per[i] += __shfl_xor_sync(0xffffffffu, per[i], off);
        }
    if (tig == 0) {
        int hd = (blockIdx.x * 128) / NF;
#pragma unroll
        for (int mt = 0; mt < 4; mt++)
#pragma unroll
            for (int hf = 0; hf < 2; hf++) {
                int n = blockIdx.y * 128 + wm + mt * 16 + hf * 8 + g;
                atomicAdd(&el[n * NH + hd], pel[mt * 2 + hf]);
                atomicAdd(&er[n * NH + hd], per[mt * 2 + hf]);
            }
    }
}

// ---------------- fp32 -> fp8 convert ----------------
__global__ void cvt8_kernel(const float* __restrict__ x, __nv_fp8_e4m3* __restrict__ o, int n) {
    int i = blockIdx.x * 256 + threadIdx.x;
    if (i < n) o[i] = __nv_fp8_e4m3(x[i]);
}

// ---------------- W[K][M] -> Bt[M][K] fp8 transpose ----------------
__global__ __launch_bounds__(256) void wtrans_kernel(
    const float* __restrict__ W, __nv_fp8_e4m3* __restrict__ Bt, int K, int M)
{
    __shared__ float t[32][33];
    int m0 = blockIdx.x * 32, k0 = blockIdx.y * 32;
    int tx = threadIdx.x & 31, ty = threadIdx.x >> 5;
#pragma unroll
    for (int i = 0; i < 32; i += 8)
        t[ty + i][tx] = W[(size_t)(k0 + ty + i) * M + m0 + tx];
    __syncthreads();
#pragma unroll
    for (int i = 0; i < 32; i += 8)
        Bt[(size_t)(m0 + ty + i) * K + k0 + tx] = __nv_fp8_e4m3(t[tx][ty + i]);
}

// ---------------- per-layer zeroing ----------------
__global__ void prep_kernel() {
    int i = blockIdx.x * 256 + threadIdx.x;
    if (i < NHD) { g_colsum[i] = 0.f; g_colsq[i] = 0.f; }
    if (i < NN * NH) { g_el[i] = 0.f; g_er[i] = 0.f; }
}

// ---------------- edge softmax + aggregation (+bias), bf16 ----------------
__global__ __launch_bounds__(256) void aggregate_kernel(
    const __nv_bfloat16* __restrict__ feat, const float* __restrict__ el,
    const float* __restrict__ er, const int* __restrict__ esrc,
    const float* __restrict__ bias, __nv_bfloat16* __restrict__ outh)
{
    int n = blockIdx.x;
    __shared__ int   ssrc[DEG];
    __shared__ float salpha[NH * DEG];
    int tid = threadIdx.x;
    if (tid < DEG) ssrc[tid] = esrc[n * DEG + tid];
    __syncthreads();
    if (tid < 32) {
        int h = tid >> 3, k = tid & 7;
        float e = el[ssrc[k] * NH + h] + er[n * NH + h];
        e = e > 0.f ? e : 0.2f * e;
        float m = e;
#pragma unroll
        for (int o = 4; o; o >>= 1) m = fmaxf(m, __shfl_xor_sync(0xffffffffu, m, o));
        float a = __expf(e - m);
        float s = a;
#pragma unroll
        for (int o = 4; o; o >>= 1) s += __shfl_xor_sync(0xffffffffu, s, o);
        salpha[tid] = a / s;
    }
    __syncthreads();
    const __nv_bfloat162* f2 = (const __nv_bfloat162*)feat;
    __nv_bfloat162* o2 = (__nv_bfloat162*)outh;
    for (int c2 = tid; c2 < NHD / 2; c2 += 256) {
        int h = c2 / (NF / 2);
        float accx = bias[2 * c2], accy = bias[2 * c2 + 1];
#pragma unroll
        for (int k = 0; k < DEG; k++) {
            float w = salpha[h * DEG + k];
            float2 v = __bfloat1622float2(f2[(size_t)ssrc[k] * (NHD / 2) + c2]);
            accx += w * v.x; accy += w * v.y;
        }
        o2[(size_t)n * (NHD / 2) + c2] = __floats2bfloat162_rn(accx, accy);
    }
}

// ---------------- column stats ----------------
__global__ __launch_bounds__(256) void colstats_kernel(const __nv_bfloat16* __restrict__ x) {
    int c2 = blockIdx.x * 256 + threadIdx.x;
    int r0 = blockIdx.y * 256;
    const __nv_bfloat162* x2 = (const __nv_bfloat162*)x;
    float s0 = 0.f, s1 = 0.f, q0 = 0.f, q1 = 0.f;
    for (int r = r0; r < r0 + 256; r++) {
        float2 v = __bfloat1622float2(x2[(size_t)r * (NHD / 2) + c2]);
        s0 += v.x; q0 += v.x * v.x;
        s1 += v.y; q1 += v.y * v.y;
    }
    atomicAdd(&g_colsum[2 * c2], s0);
    atomicAdd(&g_colsum[2 * c2 + 1], s1);
    atomicAdd(&g_colsq[2 * c2], q0);
    atomicAdd(&g_colsq[2 * c2 + 1], q1);
}

__global__ void colfin_kernel(const float* __restrict__ gamma, const float* __restrict__ beta) {
    int c = blockIdx.x * 256 + threadIdx.x;
    if (c >= NHD) return;
    float mu  = g_colsum[c] * (1.f / NN);
    float var = g_colsq[c] * (1.f / NN) - mu * mu;
    float rs  = rsqrtf(var + 1e-5f);
    float a   = rs * gamma[c];
    g_colA[c] = a;
    g_colB[c] = beta[c] - mu * a;
}

// ---------------- LN + PReLU epilogues ----------------
__global__ __launch_bounds__(256) void lnfuse1_kernel(
    const __nv_bfloat16* __restrict__ h, const float* __restrict__ pa,
    __nv_fp8_e4m3* __restrict__ a8, float* __restrict__ m1)
{
    int n = blockIdx.x;
    for (int f = threadIdx.x; f < NF; f += 256) {
        float s = 0.f;
#pragma unroll
        for (int hh = 0; hh < 4; hh++) {
            int c = hh * NF + f;
            float y = g_colA[c] * __bfloat162float(h[(size_t)n * NHD + c]) + g_colB[c];
            y = y > 0.f ? y : pa[c] * y;
            a8[(size_t)n * NHD + c] = __nv_fp8_e4m3(y);
            s += y;
        }
        m1[(size_t)n * NF + f] = 0.25f * s;
    }
}

__global__ __launch_bounds__(256) void lnfuse2_kernel(
    const __nv_bfloat16* __restrict__ h, const float* __restrict__ pa)
{
    int n = blockIdx.x;
    for (int f = threadIdx.x; f < NF; f += 256) {
        float s = 0.f;
#pragma unroll
        for (int hh = 0; hh < 4; hh++) {
            int c = hh * NF + f;
            float y = g_colA[c] * __bfloat162float(h[(size_t)n * NHD + c]) + g_colB[c];
            y = y > 0.f ? y : pa[c] * y;
            s += y;
        }
        g_rep[(size_t)n * NF + f] = fmaxf(g_m1[(size_t)n * NF + f], 0.25f * s);
    }
}

// ---------------- sims: S[128 x 8192] = Qe @ rep^T ----------------
__global__ __launch_bounds__(256) void simgemm_kernel(
    const float* __restrict__ Qe, const float* __restrict__ R)
{
    __shared__ float Qs[128][33];
    __shared__ float Rs[32][33];
    int tid = threadIdx.x;
    int n0 = blockIdx.x * 32;
    float acc[16];
#pragma unroll
    for (int i = 0; i < 16; i++) acc[i] = 0.f;
    int n = tid & 31, rb = tid >> 5;

    for (int k0 = 0; k0 < ND; k0 += 32) {
#pragma unroll
        for (int t = 0; t < 16; t++) {
            int li = tid + t * 256;
            Qs[li >> 5][li & 31] = Qe[(size_t)(li >> 5) * ND + k0 + (li & 31)];
        }
#pragma unroll
        for (int t = 0; t < 4; t++) {
            int li = tid + t * 256;
            Rs[li >> 5][li & 31] = R[(size_t)(n0 + (li >> 5)) * ND + k0 + (li & 31)];
        }
        __syncthreads();
#pragma unroll
        for (int kk = 0; kk < 32; kk++) {
            float b = Rs[n][kk];
#pragma unroll
            for (int i = 0; i < 16; i++)
                acc[i] += Qs[rb + 8 * i][kk] * b;
        }
        __syncthreads();
    }
#pragma unroll
    for (int i = 0; i < 16; i++)
        g_S[(size_t)(rb + 8 * i) * NN + n0 + n] = acc[i];
}

// ---------------- output zero ----------------
__global__ void zeroout_kernel(float* out) {
    if (threadIdx.x < 3) out[threadIdx.x] = 0.f;
}

// ---------------- losses ----------------
__device__ __forceinline__ float warpSumF(float v) {
#pragma unroll
    for (int o = 16; o; o >>= 1) v += __shfl_xor_sync(0xffffffffu, v, o);
    return v;
}

__device__ __forceinline__ float blockSumF(float v, float* sred, int tid) {
    v = warpSumF(v);
    if ((tid & 31) == 0) sred[tid >> 5] = v;
    __syncthreads();
    if (tid < 32) {
        float x = (tid < 16) ? sred[tid] : 0.f;
        x = warpSumF(x);
        if (tid == 0) sred[0] = x;
    }
    __syncthreads();
    float r = sred[0];
    __syncthreads();
    return r;
}

__device__ __forceinline__ float blockMaxF(float v, float* sred, int tid) {
#pragma unroll
    for (int o = 16; o; o >>= 1) v = fmaxf(v, __shfl_xor_sync(0xffffffffu, v, o));
    if ((tid & 31) == 0) sred[tid >> 5] = v;
    __syncthreads();
    if (tid < 32) {
        float x = (tid < 16) ? sred[tid] : -INFINITY;
#pragma unroll
        for (int o = 16; o; o >>= 1) x = fmaxf(x, __shfl_xor_sync(0xffffffffu, x, o));
        if (tid == 0) sred[0] = x;
    }
    __syncthreads();
    float r = sred[0];
    __syncthreads();
    return r;
}

__device__ void bitonic1024_desc(float* key, int* idx, int tid) {
    for (int k = 2; k <= 1024; k <<= 1) {
        for (int j = k >> 1; j > 0; j >>= 1) {
#pragma unroll 1
            for (int t = tid; t < 1024; t += 512) {
                int x = t ^ j;
                if (x > t) {
                    bool descSeg = ((t & k) == 0);
                    float ka = key[t], kb = key[x];
                    int   ia = idx[t], ib = idx[x];
                    bool aFirst = (ka > kb) || (ka == kb && ia < ib);
                    bool doSwap = descSeg ? (!aFirst) : aFirst;
                    if (doSwap) { key[t] = kb; key[x] = ka; idx[t] = ib; idx[x] = ia; }
                }
            }
            __syncthreads();
        }
    }
}

// lambda-MRR via product trick (no per-pair MUFU).
__global__ __launch_bounds__(512) void loss_kernel(const float* __restrict__ bert, float* __restrict__ out) {
    __shared__ float skey[1024];
    __shared__ int   sidx[1024];
    __shared__ float sez[1024];
    __shared__ float sred[16];
    __shared__ float sh_psim;
    int r = blockIdx.x;
    int g = r >> 4;
    int base = g * NPG;
    int tid = threadIdx.x;
    const float* Srow = g_S + (size_t)r * NN;

    skey[tid]       = bert[(size_t)r * NPG + tid];       sidx[tid]       = tid;
    skey[tid + 512] = bert[(size_t)r * NPG + tid + 512]; sidx[tid + 512] = tid + 512;
    __syncthreads();
    bitonic1024_desc(skey, sidx, tid);

    int i0 = sidx[tid], i1 = sidx[tid + 512];
    float v0 = Srow[base + i0], v1 = Srow[base + i1];
    __syncthreads();
    skey[tid] = v0;       sidx[tid] = tid;
    skey[tid + 512] = v1; sidx[tid + 512] = tid + 512;
    if (tid == 0) sh_psim = v0;
    __syncthreads();

    bitonic1024_desc(skey, sidx, tid);

    {
        float y0 = skey[0];
        sez[tid]       = __expf(fmaxf(skey[tid]       - y0, -60.f));
        sez[tid + 512] = __expf(fmaxf(skey[tid + 512] - y0, -60.f));
    }
    __syncthreads();

    int wid = tid >> 5, lane = tid & 31;
    float uacc = 0.f, tacc = 0.f;
#pragma unroll 1
    for (int half = 0; half < 2; half++) {
        int c = half ? (31 - wid) : wid;
        int i = c * 32 + lane;
        float yi = skey[i];
        int   pi = sidx[i];
        float inv = __fdividef(1.f, sez[i]);
        float ts0 = 0.f, ts1 = 0.f, ts2 = 0.f, ts3 = 0.f;
#pragma unroll 1
        for (int jb = c * 32; jb < 1024; jb += 32) {
            float p0 = 1.f, p1 = 1.f, p2 = 1.f, p3 = 1.f;
#pragma unroll
            for (int q4 = 0; q4 < 8; q4++) {
                int j4 = jb + q4 * 4;
                float4 y4 = *(const float4*)&skey[j4];
                float4 e4 = *(const float4*)&sez[j4];
                int4   p4 = *(const int4*)&sidx[j4];
                {   bool act = (j4 + 0) > i;
                    p0 *= act ? fmaf(e4.x, inv, 1.f) : 1.f;
                    float t = fminf(yi - y4.x, 50.f);
                    if (act && pi > p4.x) ts0 += t; }
                {   bool act = (j4 + 1) > i;
                    p1 *= act ? fmaf(e4.y, inv, 1.f) : 1.f;
                    float t = fminf(yi - y4.y, 50.f);
                    if (act && pi > p4.y) ts1 += t; }
                {   bool act = (j4 + 2) > i;
                    p2 *= act ? fmaf(e4.z, inv, 1.f) : 1.f;
                    float t = fminf(yi - y4.z, 50.f);
                    if (act && pi > p4.z) ts2 += t; }
                {   bool act = (j4 + 3) > i;
                    p3 *= act ? fmaf(e4.w, inv, 1.f) : 1.f;
                    float t = fminf(yi - y4.w, 50.f);
                    if (act && pi > p4.w) ts3 += t; }
            }
            uacc += __logf((p0 * p1) * (p2 * p3));
        }
        tacc += (ts0 + ts1) + (ts2 + ts3);
    }
    float Ltot = blockSumF(uacc + tacc, sred, tid);

    float mx = -INFINITY;
    for (int c = tid; c < NN; c += 512) mx = fmaxf(mx, Srow[c]);
    float m = blockMaxF(mx, sred, tid);

    float se = 0.f, s1 = 0.f, s2 = 0.f;
    for (int c = tid; c < NN; c += 512) {
        float x = Srow[c] - m;
        float e = __expf(x);
        se += e;
        if (c >= base && c < base + NPG) { s1 += e; s2 += x * e; }
    }
    se = blockSumF(se, sred, tid);
    s1 = blockSumF(s1, sred, tid);
    s2 = blockSumF(s2, sred, tid);

    if (tid == 0) {
        float lse = m + __logf(se);
        float cl  = lse - sh_psim;
        float ent = __logf(s1) - s2 / s1;
        atomicAdd(out + 0, cl  * (1.f / 128.f));
        atomicAdd(out + 2, ent * (1.f / 128.f));
        atomicAdd(out + 1, Ltot * (1.f / 67043328.f));
    }
}

// ---------------- launch ----------------
extern "C" void kernel_launch(void* const* d_in, const int* in_sizes, int n_in,
                              void* d_out, int out_size) {
    const float* x      = (const float*)d_in[0];
    const int*   esrc   = (const int*)d_in[1];
    const float* qe     = (const float*)d_in[3];
    const float* bert   = (const float*)d_in[4];
    const float* W1     = (const float*)d_in[5];
    const float* al1    = (const float*)d_in[6];
    const float* ar1    = (const float*)d_in[7];
    const float* b1     = (const float*)d_in[8];
    const float* gamma1 = (const float*)d_in[9];
    const float* beta1  = (const float*)d_in[10];
    const float* pa1    = (const float*)d_in[11];
    const float* W2     = (const float*)d_in[12];
    const float* al2    = (const float*)d_in[13];
    const float* ar2    = (const float*)d_in[14];
    const float* b2     = (const float*)d_in[15];
    const float* gamma2 = (const float*)d_in[16];
    const float* beta2  = (const float*)d_in[17];
    const float* pa2    = (const float*)d_in[18];
    float* out = (float*)d_out;

    float *el, *er, *m1, *rep;
    __nv_bfloat16 *feat16, *h16;
    __nv_fp8_e4m3 *a8, *bT8;
    cudaGetSymbolAddress((void**)&feat16, g_feat16);
    cudaGetSymbolAddress((void**)&h16,    g_h16);
    cudaGetSymbolAddress((void**)&el,     g_el);
    cudaGetSymbolAddress((void**)&er,     g_er);
    cudaGetSymbolAddress((void**)&m1,     g_m1);
    cudaGetSymbolAddress((void**)&rep,    g_rep);
    cudaGetSymbolAddress((void**)&a8,     g_a8);
    cudaGetSymbolAddress((void**)&bT8,    g_bT8);

    cudaFuncSetAttribute(fp8_gemm_kernel,
                         cudaFuncAttributeMaxDynamicSharedMemorySize, GEMM_SMEM);

    dim3 gGemm(NHD / 128, NN / 128);       // (24, 64)
    dim3 gStats(NHD / 512, NN / 256);      // (6, 32)

    zeroout_kernel<<<1, 32>>>(out);

    // ---- layer 1 ----
    cvt8_kernel<<<(NN * ND + 255) / 256, 256>>>(x, a8, NN * ND);
    wtrans_kernel<<<dim3(NHD / 32, ND / 32), 256>>>(W1, bT8, ND, NHD);
    prep_kernel<<<(NN * NH + 255) / 256, 256>>>();
    fp8_gemm_kernel<<<gGemm, 256, GEMM_SMEM>>>(a8, bT8, feat16, ND, al1, ar1, el, er);
    aggregate_kernel<<<NN, 256>>>(feat16, el, er, esrc, b1, h16);
    colstats_kernel<<<gStats, 256>>>(h16);
    colfin_kernel<<<NHD / 256, 256>>>(gamma1, beta1);
    lnfuse1_kernel<<<NN, 256>>>(h16, pa1, a8, m1);

    // ---- layer 2 ----
    wtrans_kernel<<<dim3(NHD / 32, NHD / 32), 256>>>(W2, bT8, NHD, NHD);
    prep_kernel<<<(NN * NH + 255) / 256, 256>>>();
    fp8_gemm_kernel<<<gGemm, 256, GEMM_SMEM>>>(a8, bT8, feat16, NHD, al2, ar2, el, er);
    aggregate_kernel<<<NN, 256>>>(feat16, el, er, esrc, b2, h16);
    colstats_kernel<<<gStats, 256>>>(h16);
    colfin_kernel<<<NHD / 256, 256>>>(gamma2, beta2);
    lnfuse2_kernel<<<NN, 256>>>(h16, pa2);

    // ---- similarities + losses ----
    simgemm_kernel<<<NN / 32, 256>>>(qe, rep);
    loss_kernel<<<NROW, 512>>>(bert, out);
}